// round 1
// baseline (speedup 1.0000x reference)
#include <cuda_runtime.h>
#include <cstdint>

// ============================================================================
// TensorContractionLayer: 3 outputs, each node_s = X_s(4096x4096) @ C_s(4096x256)
//   C_s[(hi,lo)][(p,q)] = sum_t P[.,p,t] * Q[.,t,q]   (chain of two cores)
//   skip 0: P=core1(hi=n1), Q=core2(lo=n2); X row=(b,n0): x stride r=4096, hi=64,  lo=1
//   skip 1: P=core2(lo=n2), Q=core0(hi=n0); X row=(b,n1): x stride r=64,   hi=4096,lo=1
//   skip 2: P=core0(hi=n0), Q=core1(lo=n1); X row=(b,n2): x stride r=1,    hi=4096,lo=64
// (skip-1 k-order deliberately permuted to n0*64+n2 so lo is unit-stride.)
// ============================================================================

#define KDIM 4096
#define NDIM 256
#define BM 64
#define BN 128
#define BK 16
#define NT (KDIM / BK)
#define NODE_ELEMS (64 * 64 * 16 * 16)  // 1048576

__device__ float g_chains[3][KDIM * NDIM];  // 12 MB scratch (static: no alloc)

__device__ __forceinline__ void cp_async16(uint32_t smem_addr, const void* gmem) {
    asm volatile("cp.async.cg.shared.global [%0], [%1], 16;\n" :: "r"(smem_addr), "l"(gmem));
}
__device__ __forceinline__ void cp_commit() {
    asm volatile("cp.async.commit_group;\n" ::: "memory");
}
template <int N>
__device__ __forceinline__ void cp_wait() {
    asm volatile("cp.async.wait_group %0;\n" :: "n"(N) : "memory");
}

// ----------------------------------------------------------------------------
// Chain precompute: C_s[(hi*64+lo)*256 + p*16+q]
// grid (64, 3), 256 threads. Tiny (~33 MFLOP total).
// ----------------------------------------------------------------------------
__global__ void __launch_bounds__(256) chain_kernel(const float* __restrict__ c0,
                                                    const float* __restrict__ c1,
                                                    const float* __restrict__ c2) {
    const int s = blockIdx.y;
    const int hi = blockIdx.x;
    const int tid = threadIdx.x;
    const float* P;
    const float* Q;
    bool hiP;
    if (s == 0)      { P = c1; Q = c2; hiP = true;  }
    else if (s == 1) { P = c2; Q = c0; hiP = false; }
    else             { P = c0; Q = c1; hiP = true;  }

    __shared__ float sm[256];  // the core slice indexed by 'hi'
    sm[tid] = hiP ? P[hi * 256 + tid] : Q[hi * 256 + tid];
    __syncthreads();

    const int p = tid >> 4;
    const int q = tid & 15;
    float* C = g_chains[s];

    for (int lo = 0; lo < 64; lo++) {
        float acc = 0.f;
        if (hiP) {
            // C = sum_t P[hi,p,t] * Q[lo,t,q]
#pragma unroll
            for (int t = 0; t < 16; t++) acc += sm[p * 16 + t] * Q[lo * 256 + t * 16 + q];
        } else {
            // C = sum_t P[lo,p,t] * Q[hi,t,q]
#pragma unroll
            for (int t = 0; t < 16; t++) acc += P[lo * 256 + p * 16 + t] * sm[t * 16 + q];
        }
        C[(hi * 64 + lo) * 256 + tid] = acc;
    }
}

// ----------------------------------------------------------------------------
// GEMM: per (b-tile, n-tile, skip). BM=64 rows (one full b), BN=128, BK=16.
// 256 threads, 8x4 register tile, cp.async double buffer.
// ----------------------------------------------------------------------------
template <int SKIP>
__device__ __forceinline__ void gemm_body(const float* __restrict__ x,
                                          float* __restrict__ out,
                                          float* smem) {
    constexpr int SR = (SKIP == 0) ? 4096 : (SKIP == 1) ? 64 : 1;   // row (n_s) stride
    constexpr int SH = (SKIP == 0) ? 64 : 4096;                      // k-hi stride
    // k-lo stride: 1 for SKIP 0/1 (vectorize along k), 64 for SKIP 2 (vectorize along rows)

    const int tid = threadIdx.x;
    const int b = blockIdx.x;
    const int nt = blockIdx.y;
    const float* xb = x + b * 262144;
    const float* Cg = g_chains[SKIP];

    // smem layout (floats): Xs[2] @ 0,1024 ; Cs[2] @ 2048,4096. Total 6144 f = 24 KB.
    const uint32_t sbase = (uint32_t)__cvta_generic_to_shared(smem);

    // X load role
    int xr, xkl;
    if (SKIP == 2) { xkl = tid >> 4; xr = (tid & 15) * 4; }   // float4 along rows
    else           { xr = tid >> 2; xkl = (tid & 3) * 4; }    // float4 along k (lo)

    auto load_tile = [&](int kt, int buf) {
        const int k0 = kt * BK;
        const int khi = k0 >> 6;
        const int klo = k0 & 63;
        // X tile
        if (SKIP == 2) {
            // addr = xb + khi*4096 + (klo+xkl)*64 + xr ; smem Xs[buf][xkl*BM + xr]
            const float* g = xb + khi * 4096 + (klo + xkl) * 64 + xr;
            uint32_t sa = sbase + (buf * 1024 + xkl * BM + xr) * 4;
            cp_async16(sa, g);
        } else {
            // addr = xb + SR*xr + SH*khi + (klo + xkl) ; smem Xs[buf][xr*BK + xkl]
            const float* g = xb + SR * xr + SH * khi + klo + xkl;
            uint32_t sa = sbase + (buf * 1024 + xr * BK + xkl) * 4;
            cp_async16(sa, g);
        }
        // C tile: 16 rows x 128 cols = 512 float4, 2 per thread
#pragma unroll
        for (int i = 0; i < 2; i++) {
            const int f = tid + i * 256;
            const int row = f >> 5;
            const int col = (f & 31) * 4;
            const float* g = Cg + (k0 + row) * NDIM + nt * BN + col;
            uint32_t sa = sbase + (2048 + buf * 2048 + row * BN + col) * 4;
            cp_async16(sa, g);
        }
    };

    const int tc = tid & 31;  // col group: cols nt*128 + tc*4 .. +3
    const int tr = tid >> 5;  // row group: rows tr*8 .. +7

    float acc[8][4];
#pragma unroll
    for (int i = 0; i < 8; i++)
#pragma unroll
        for (int j = 0; j < 4; j++) acc[i][j] = 0.f;

    load_tile(0, 0);
    cp_commit();

    for (int kt = 0; kt < NT; kt++) {
        const int cur = kt & 1;
        if (kt + 1 < NT) {
            load_tile(kt + 1, cur ^ 1);
            cp_commit();
            cp_wait<1>();
        } else {
            cp_wait<0>();
        }
        __syncthreads();

        const float* xsC = smem + cur * 1024;
        const float* csC = smem + 2048 + cur * 2048;

#pragma unroll
        for (int k = 0; k < BK; k++) {
            float a[8];
            if (SKIP == 2) {
                float4 a0 = *(const float4*)(xsC + k * BM + tr * 8);
                float4 a1 = *(const float4*)(xsC + k * BM + tr * 8 + 4);
                a[0] = a0.x; a[1] = a0.y; a[2] = a0.z; a[3] = a0.w;
                a[4] = a1.x; a[5] = a1.y; a[6] = a1.z; a[7] = a1.w;
            } else {
#pragma unroll
                for (int i = 0; i < 8; i++) a[i] = xsC[(tr * 8 + i) * BK + k];
            }
            float4 bv = *(const float4*)(csC + k * BN + tc * 4);
#pragma unroll
            for (int i = 0; i < 8; i++) {
                acc[i][0] += a[i] * bv.x;
                acc[i][1] += a[i] * bv.y;
                acc[i][2] += a[i] * bv.z;
                acc[i][3] += a[i] * bv.w;
            }
        }
        __syncthreads();
    }

    // epilogue: rows b*64 + tr*8 + i, cols nt*128 + tc*4
    float* ob = out + (b * 64 + tr * 8) * NDIM + nt * BN + tc * 4;
#pragma unroll
    for (int i = 0; i < 8; i++) {
        float4 v = make_float4(acc[i][0], acc[i][1], acc[i][2], acc[i][3]);
        *(float4*)(ob + i * NDIM) = v;
    }
}

__global__ void __launch_bounds__(256) gemm_kernel(const float* __restrict__ x,
                                                   float* __restrict__ out) {
    __shared__ float smem[6144];
    const int s = blockIdx.z;
    if (s == 0)      gemm_body<0>(x, out, smem);
    else if (s == 1) gemm_body<1>(x, out + NODE_ELEMS, smem);
    else             gemm_body<2>(x, out + 2 * NODE_ELEMS, smem);
}

// ----------------------------------------------------------------------------
extern "C" void kernel_launch(void* const* d_in, const int* in_sizes, int n_in,
                              void* d_out, int out_size) {
    const float* x  = (const float*)d_in[0];
    const float* c0 = (const float*)d_in[1];
    const float* c1 = (const float*)d_in[2];
    const float* c2 = (const float*)d_in[3];
    float* out = (float*)d_out;

    chain_kernel<<<dim3(64, 3), 256>>>(c0, c1, c2);
    gemm_kernel<<<dim3(64, 2, 3), 256>>>(x, out);
}

// round 4
// speedup vs baseline: 1.8480x; 1.8480x over previous
#include <cuda_runtime.h>
#include <cuda_fp16.h>
#include <cstdint>

// ============================================================================
// node_s (4096x256) = X_s (4096x4096) @ C_s^T  via mma.sync fp16 (2-product
// split: X = Ah + Al in fp16; C single fp16 -> rel_err ~ 2^-11/sqrt(3)).
//   skip0: rows (b,n0), k=(n1,n2) -> X = x straight
//   skip1: rows (b,n1), k=(n0,n2) -> gather 64-row blocks of straight x
//   skip2: rows (b,n2), k=(n1,n0) -> X = x_T[b][n2][n1][n0]
// C_s stored [256 pq][4096 k] k-contiguous (row.col B operand).
// ============================================================================

#define BM 128
#define BN 128
#define BK 32
#define NCHUNK 128
#define PITCH 80                    // 32 fp16 = 64B + 16B pad: conflict-free ldsm
#define APART (BM * PITCH)          // 10240
#define STAGE_BYTES (3 * APART)     // Ah | Al | B
#define NSTAGE 3
#define SMEM_TOTAL (STAGE_BYTES * NSTAGE)  // 92160

// ---- scratch (device globals: no allocation) ----
__device__ __align__(1024) __half g_xh[16777216];   // [b][n0][n1][n2] hi
__device__ __align__(1024) __half g_xl[16777216];   // lo
__device__ __align__(1024) __half g_xth[16777216];  // [b][n2][n1][n0] hi
__device__ __align__(1024) __half g_xtl[16777216];  // lo
__device__ __align__(1024) __half g_c[3u * 256 * 4096];  // chains [s][pq][k]

// ---- PTX helpers ----
__device__ __forceinline__ uint32_t smem_u32(const void* p) {
    uint32_t a;
    asm("{ .reg .u64 t; cvta.to.shared.u64 t, %1; cvt.u32.u64 %0, t; }" : "=r"(a) : "l"(p));
    return a;
}
__device__ __forceinline__ void cp_async16(uint32_t s, const void* g) {
    asm volatile("cp.async.cg.shared.global [%0], [%1], 16;\n" :: "r"(s), "l"(g));
}
__device__ __forceinline__ void cp_commit() { asm volatile("cp.async.commit_group;\n" ::: "memory"); }
template <int N> __device__ __forceinline__ void cp_wait() {
    asm volatile("cp.async.wait_group %0;\n" :: "n"(N) : "memory");
}
__device__ __forceinline__ void ldsm_x4(uint32_t& r0, uint32_t& r1, uint32_t& r2,
                                        uint32_t& r3, uint32_t addr) {
    asm volatile("ldmatrix.sync.aligned.m8n8.x4.shared.b16 {%0,%1,%2,%3}, [%4];"
                 : "=r"(r0), "=r"(r1), "=r"(r2), "=r"(r3) : "r"(addr));
}
__device__ __forceinline__ void mma16816(float* d, const uint32_t* a, uint32_t b0, uint32_t b1) {
    asm volatile("mma.sync.aligned.m16n8k16.row.col.f32.f16.f16.f32 "
                 "{%0,%1,%2,%3},{%4,%5,%6,%7},{%8,%9},{%0,%1,%2,%3};"
                 : "+f"(d[0]), "+f"(d[1]), "+f"(d[2]), "+f"(d[3])
                 : "r"(a[0]), "r"(a[1]), "r"(a[2]), "r"(a[3]), "r"(b0), "r"(b1));
}

// ============================================================================
// prep: x fp32 -> fp16 hi/lo, straight [b][n0][n1][n2] and reversed
// [b][n2][n1][n0]. grid(64 n1, 64 b), 256 threads.
// ============================================================================
__global__ void __launch_bounds__(256) prep_kernel(const float* __restrict__ x) {
    __shared__ float tile[64][65];
    const int n1 = blockIdx.x, b = blockIdx.y, tid = threadIdx.x;
    const size_t base = (size_t)b * 262144 + (size_t)n1 * 64;
#pragma unroll
    for (int i = 0; i < 16; i++) {
        int lin = tid + i * 256;
        int r = lin >> 6, c = lin & 63;  // r=n0, c=n2
        tile[r][c] = x[base + (size_t)r * 4096 + c];
    }
    __syncthreads();
#pragma unroll
    for (int i = 0; i < 16; i++) {
        int lin = tid + i * 256;
        int r = lin >> 6, c = lin & 63;
        float v = tile[r][c];  // straight: [b][n0=r][n1][n2=c]
        __half h = __float2half_rn(v);
        g_xh[base + (size_t)r * 4096 + c] = h;
        g_xl[base + (size_t)r * 4096 + c] = __float2half_rn(v - __half2float(h));
        float vt = tile[c][r];  // reversed: [b][n2=r][n1][n0=c]
        __half ht = __float2half_rn(vt);
        g_xth[base + (size_t)r * 4096 + c] = ht;
        g_xtl[base + (size_t)r * 4096 + c] = __float2half_rn(vt - __half2float(ht));
    }
}

// ============================================================================
// chain: C_s[pq][u*64+v] fp16. grid(64 u, 3 s), 256 thr = (p,q)
//   s0: u=n1,v=n2: core1[u][p][t]*core2[v][t][q]
//   s1: u=n0,v=n2: core2[v][p][t]*core0[u][t][q]
//   s2: u=n1,v=n0: core0[v][p][t]*core1[u][t][q]
// ============================================================================
__global__ void __launch_bounds__(256) chain_kernel(const float* __restrict__ c0,
                                                    const float* __restrict__ c1,
                                                    const float* __restrict__ c2) {
    const int u = blockIdx.x, s = blockIdx.y, tid = threadIdx.x;
    const int p = tid >> 4, q = tid & 15;
    __shared__ float U[256], V[256];
    const float* Uc = (s == 1) ? c0 : c1;
    const float* Vc = (s == 2) ? c0 : c2;
    U[tid] = Uc[u * 256 + tid];
    __syncthreads();
    float vals[64];
#pragma unroll
    for (int v = 0; v < 64; v++) {
        V[tid] = Vc[v * 256 + tid];
        __syncthreads();
        float acc = 0.f;
        if (s == 0) {
#pragma unroll
            for (int t = 0; t < 16; t++) acc += U[p * 16 + t] * V[t * 16 + q];
        } else {
#pragma unroll
            for (int t = 0; t < 16; t++) acc += V[p * 16 + t] * U[t * 16 + q];
        }
        vals[v] = acc;
        __syncthreads();
    }
    const size_t o = (size_t)s * 1048576 + (size_t)tid * 4096 + (size_t)u * 64;
#pragma unroll
    for (int v = 0; v < 64; v++) g_c[o + v] = __float2half_rn(vals[v]);
}

// ============================================================================
// GEMM: grid(32 m, 2 n, 3 skip), 256 threads (8 warps 2x4; warp tile 64x32).
// 3-stage cp.async pipeline; per chunk: 2 ksteps x (Ah,Al)x(4 m-frags)x(4 n-frags).
// ============================================================================
template <int SKIP>
__device__ __forceinline__ void gemm_body(float* __restrict__ out) {
    extern __shared__ char smem[];
    const uint32_t sb = smem_u32(smem);
    const int tid = threadIdx.x, lane = tid & 31, wid = tid >> 5;
    const int wm = wid >> 2, wn = wid & 3;
    const int m0 = blockIdx.x * BM, n0 = blockIdx.y * BN;

    const __half* Ah = (SKIP == 2) ? g_xth : g_xh;
    const __half* Al = (SKIP == 2) ? g_xtl : g_xl;
    const __half* B = g_c + (size_t)SKIP * 1048576;

    // cp.async roles: 2 iters, lin = tid + i*256 -> row = lin>>2 (0..127), c16 = lin&3
    auto load = [&](int chunk, int st) {
        const uint32_t stg = sb + st * STAGE_BYTES;
#pragma unroll
        for (int i = 0; i < 2; i++) {
            const int lin = tid + i * 256;
            const int r = lin >> 2, c = lin & 3;
            size_t offA;
            if (SKIP == 1) {
                const int bb = (m0 >> 6) + (r >> 6), nn1 = r & 63;
                const int nn0 = chunk >> 1, nn2 = ((chunk & 1) << 5) + (c << 3);
                offA = ((size_t)bb << 18) + ((size_t)nn0 << 12) + (nn1 << 6) + nn2;
            } else {
                offA = ((size_t)(m0 + r) << 12) + (chunk << 5) + (c << 3);
            }
            const uint32_t sa = stg + r * PITCH + c * 16;
            cp_async16(sa, Ah + offA);
            cp_async16(sa + APART, Al + offA);
            cp_async16(sa + 2 * APART, B + ((size_t)(n0 + r) << 12) + (chunk << 5) + (c << 3));
        }
        cp_commit();
    };

    float acc[4][4][4];
#pragma unroll
    for (int fm = 0; fm < 4; fm++)
#pragma unroll
        for (int fn = 0; fn < 4; fn++)
#pragma unroll
            for (int j = 0; j < 4; j++) acc[fm][fn][j] = 0.f;

    load(0, 0); load(1, 1); load(2, 2);

    // per-thread ldsm byte offsets (within a stage part)
    const uint32_t aoff = (wm * 64 + (lane & 15)) * PITCH + (lane >> 4) * 16;
    const uint32_t boff = (wn * 32 + (lane & 15)) * PITCH + (lane >> 4) * 16;

    for (int c = 0; c < NCHUNK; c++) {
        const int st = c % NSTAGE;
        if (c < NCHUNK - 2)       cp_wait<2>();
        else if (c == NCHUNK - 2) cp_wait<1>();
        else                      cp_wait<0>();
        __syncthreads();
        const uint32_t stg = sb + st * STAGE_BYTES;
#pragma unroll
        for (int ks = 0; ks < 2; ks++) {
            uint32_t b[2][4];
#pragma unroll
            for (int fp = 0; fp < 2; fp++)
                ldsm_x4(b[fp][0], b[fp][1], b[fp][2], b[fp][3],
                        stg + 2 * APART + boff + fp * (16 * PITCH) + ks * 32);
#pragma unroll
            for (int fm = 0; fm < 4; fm++) {
                uint32_t a4[4];
                ldsm_x4(a4[0], a4[1], a4[2], a4[3],
                        stg + aoff + fm * (16 * PITCH) + ks * 32);
#pragma unroll
                for (int fn = 0; fn < 4; fn++)
                    mma16816(acc[fm][fn], a4, b[fn >> 1][fn & 1], b[fn >> 1][(fn & 1) + 2]);
                ldsm_x4(a4[0], a4[1], a4[2], a4[3],
                        stg + APART + aoff + fm * (16 * PITCH) + ks * 32);
#pragma unroll
                for (int fn = 0; fn < 4; fn++)
                    mma16816(acc[fm][fn], a4, b[fn >> 1][fn & 1], b[fn >> 1][(fn & 1) + 2]);
            }
        }
        __syncthreads();
        if (c + NSTAGE < NCHUNK) load(c + NSTAGE, st);
    }

    // epilogue: d0,d1 -> (row, col..col+1); d2,d3 -> (row+8, ...)
    float* outp = out + (size_t)SKIP * 1048576;
    const int rbase = m0 + wm * 64 + (lane >> 2);
    const int cbase = n0 + wn * 32 + (lane & 3) * 2;
#pragma unroll
    for (int fm = 0; fm < 4; fm++)
#pragma unroll
        for (int fn = 0; fn < 4; fn++) {
            const int rr = rbase + fm * 16;
            const int cc = cbase + fn * 8;
            float2 v0 = make_float2(acc[fm][fn][0], acc[fm][fn][1]);
            float2 v1 = make_float2(acc[fm][fn][2], acc[fm][fn][3]);
            *(float2*)(outp + (size_t)rr * 256 + cc) = v0;
            *(float2*)(outp + (size_t)(rr + 8) * 256 + cc) = v1;
        }
}

__global__ void __launch_bounds__(256, 2) gemm_kernel(float* __restrict__ out) {
    if (blockIdx.z == 0)      gemm_body<0>(out);
    else if (blockIdx.z == 1) gemm_body<1>(out);
    else                      gemm_body<2>(out);
}

// ----------------------------------------------------------------------------
extern "C" void kernel_launch(void* const* d_in, const int* in_sizes, int n_in,
                              void* d_out, int out_size) {
    const float* x  = (const float*)d_in[0];
    const float* c0 = (const float*)d_in[1];
    const float* c1 = (const float*)d_in[2];
    const float* c2 = (const float*)d_in[3];
    float* out = (float*)d_out;

    cudaFuncSetAttribute(gemm_kernel, cudaFuncAttributeMaxDynamicSharedMemorySize, SMEM_TOTAL);
    prep_kernel<<<dim3(64, 64), 256>>>(x);
    chain_kernel<<<dim3(64, 3), 256>>>(c0, c1, c2);
    gemm_kernel<<<dim3(32, 2, 3), 256, SMEM_TOTAL>>>(out);
}

// round 5
// speedup vs baseline: 1.8705x; 1.0122x over previous
#include <cuda_runtime.h>
#include <cuda_fp16.h>
#include <cstdint>

// ============================================================================
// node_s (4096x256) = X_s (4096x4096) @ C_s^T  via mma.sync fp16 (2-product
// split: X = Ah + Al in fp16; C single fp16).
//   skip0: rows (b,n0), k=(n1,n2) -> X = x straight
//   skip1: rows (b,n1), k=(n0,n2) -> gather 64-row blocks of straight x
//   skip2: rows (b,n2), k=(n1,n0) -> X = x_T[b][n2][n1][n0]
// C_s stored [256 pq][4096 k] k-contiguous (row.col B operand).
// Mainloop: 3-stage cp.async, ONE sync per chunk, loads before compute.
// ============================================================================

#define BM 128
#define BN 128
#define NCHUNK 128
#define PITCH 80                    // 32 fp16 = 64B + 16B pad: conflict-free ldsm
#define APART (BM * PITCH)          // 10240
#define STAGE_BYTES (3 * APART)     // Ah | Al | B
#define NSTAGE 3
#define SMEM_TOTAL (STAGE_BYTES * NSTAGE)  // 92160

// ---- scratch (device globals: no allocation) ----
__device__ __align__(1024) __half g_xh[16777216];   // [b][n0][n1][n2] hi
__device__ __align__(1024) __half g_xl[16777216];   // lo
__device__ __align__(1024) __half g_xth[16777216];  // [b][n2][n1][n0] hi
__device__ __align__(1024) __half g_xtl[16777216];  // lo
__device__ __align__(1024) __half g_c[3u * 256 * 4096];  // chains [s][pq][k]

// ---- PTX helpers ----
__device__ __forceinline__ uint32_t smem_u32(const void* p) {
    uint32_t a;
    asm("{ .reg .u64 t; cvta.to.shared.u64 t, %1; cvt.u32.u64 %0, t; }" : "=r"(a) : "l"(p));
    return a;
}
__device__ __forceinline__ void cp_async16(uint32_t s, const void* g) {
    asm volatile("cp.async.cg.shared.global [%0], [%1], 16;\n" :: "r"(s), "l"(g));
}
__device__ __forceinline__ void cp_commit() { asm volatile("cp.async.commit_group;\n" ::: "memory"); }
template <int N> __device__ __forceinline__ void cp_wait() {
    asm volatile("cp.async.wait_group %0;\n" :: "n"(N) : "memory");
}
__device__ __forceinline__ void ldsm_x4(uint32_t& r0, uint32_t& r1, uint32_t& r2,
                                        uint32_t& r3, uint32_t addr) {
    asm volatile("ldmatrix.sync.aligned.m8n8.x4.shared.b16 {%0,%1,%2,%3}, [%4];"
                 : "=r"(r0), "=r"(r1), "=r"(r2), "=r"(r3) : "r"(addr));
}
__device__ __forceinline__ void mma16816(float* d, const uint32_t* a, uint32_t b0, uint32_t b1) {
    asm volatile("mma.sync.aligned.m16n8k16.row.col.f32.f16.f16.f32 "
                 "{%0,%1,%2,%3},{%4,%5,%6,%7},{%8,%9},{%0,%1,%2,%3};"
                 : "+f"(d[0]), "+f"(d[1]), "+f"(d[2]), "+f"(d[3])
                 : "r"(a[0]), "r"(a[1]), "r"(a[2]), "r"(a[3]), "r"(b0), "r"(b1));
}

// ============================================================================
// prep: x fp32 -> fp16 hi/lo, straight [b][n0][n1][n2] + reversed [b][n2][n1][n0].
// grid(64 n1, 64 b), 256 threads; 16B-vectorized loads and stores.
// Thread t: row r = t>>2 (n0 on load), cols cs = (t&3)*16 .. +15.
// ============================================================================
__global__ void __launch_bounds__(256) prep_kernel(const float* __restrict__ x) {
    __shared__ float tile[64][65];
    const int n1 = blockIdx.x, b = blockIdx.y, tid = threadIdx.x;
    const size_t base = (size_t)b * 262144 + (size_t)n1 * 64;
    const int r = tid >> 2, cs = (tid & 3) * 16;

#pragma unroll
    for (int j = 0; j < 4; j++) {
        float4 v = *(const float4*)(x + base + (size_t)r * 4096 + cs + j * 4);
        tile[r][cs + j * 4 + 0] = v.x;
        tile[r][cs + j * 4 + 1] = v.y;
        tile[r][cs + j * 4 + 2] = v.z;
        tile[r][cs + j * 4 + 3] = v.w;
    }
    __syncthreads();

    __half hb[16], lb[16], hbt[16], lbt[16];
#pragma unroll
    for (int k = 0; k < 16; k++) {
        float v = tile[r][cs + k];        // straight [b][n0=r][n1][n2=cs+k]
        __half h = __float2half_rn(v);
        hb[k] = h;
        lb[k] = __float2half_rn(v - __half2float(h));
        float vt = tile[cs + k][r];       // reversed [b][n2=r][n1][n0=cs+k]
        __half ht = __float2half_rn(vt);
        hbt[k] = ht;
        lbt[k] = __float2half_rn(vt - __half2float(ht));
    }
    const size_t o = base + (size_t)r * 4096 + cs;
#pragma unroll
    for (int j = 0; j < 2; j++) {
        *(float4*)(g_xh + o + j * 8)  = ((const float4*)hb)[j];
        *(float4*)(g_xl + o + j * 8)  = ((const float4*)lb)[j];
        *(float4*)(g_xth + o + j * 8) = ((const float4*)hbt)[j];
        *(float4*)(g_xtl + o + j * 8) = ((const float4*)lbt)[j];
    }
}

// ============================================================================
// chain: C_s[pq][u*64+v] fp16. grid(64 u, 3 s), 256 thr = (p,q)
//   s0: u=n1,v=n2: core1[u][p][t]*core2[v][t][q]
//   s1: u=n0,v=n2: core2[v][p][t]*core0[u][t][q]
//   s2: u=n1,v=n0: core0[v][p][t]*core1[u][t][q]
// ============================================================================
__global__ void __launch_bounds__(256) chain_kernel(const float* __restrict__ c0,
                                                    const float* __restrict__ c1,
                                                    const float* __restrict__ c2) {
    const int u = blockIdx.x, s = blockIdx.y, tid = threadIdx.x;
    const int p = tid >> 4, q = tid & 15;
    __shared__ float U[256], V[256];
    const float* Uc = (s == 1) ? c0 : c1;
    const float* Vc = (s == 2) ? c0 : c2;
    U[tid] = Uc[u * 256 + tid];
    __syncthreads();
    float vals[64];
#pragma unroll
    for (int v = 0; v < 64; v++) {
        V[tid] = Vc[v * 256 + tid];
        __syncthreads();
        float acc = 0.f;
        if (s == 0) {
#pragma unroll
            for (int t = 0; t < 16; t++) acc += U[p * 16 + t] * V[t * 16 + q];
        } else {
#pragma unroll
            for (int t = 0; t < 16; t++) acc += V[p * 16 + t] * U[t * 16 + q];
        }
        vals[v] = acc;
        __syncthreads();
    }
    const size_t o = (size_t)s * 1048576 + (size_t)tid * 4096 + (size_t)u * 64;
#pragma unroll
    for (int v = 0; v < 64; v++) g_c[o + v] = __float2half_rn(vals[v]);
}

// ============================================================================
// GEMM: grid(32 m, 2 n, 3 skip), 256 threads (8 warps 2x4; warp tile 64x32).
// 3-stage pipeline, one __syncthreads per chunk, loads issued before compute.
// ============================================================================
template <int SKIP>
__device__ __forceinline__ void gemm_body(float* __restrict__ out) {
    extern __shared__ char smem[];
    const uint32_t sb = smem_u32(smem);
    const int tid = threadIdx.x, lane = tid & 31, wid = tid >> 5;
    const int wm = wid >> 2, wn = wid & 3;
    const int m0 = blockIdx.x * BM, n0 = blockIdx.y * BN;

    const __half* Ah = (SKIP == 2) ? g_xth : g_xh;
    const __half* Al = (SKIP == 2) ? g_xtl : g_xl;
    const __half* B = g_c + (size_t)SKIP * 1048576;

    auto load = [&](int chunk, int st) {
        const uint32_t stg = sb + st * STAGE_BYTES;
#pragma unroll
        for (int i = 0; i < 2; i++) {
            const int lin = tid + i * 256;
            const int r = lin >> 2, c = lin & 3;
            size_t offA;
            if (SKIP == 1) {
                const int bb = (m0 >> 6) + (r >> 6), nn1 = r & 63;
                const int nn0 = chunk >> 1, nn2 = ((chunk & 1) << 5) + (c << 3);
                offA = ((size_t)bb << 18) + ((size_t)nn0 << 12) + (nn1 << 6) + nn2;
            } else {
                offA = ((size_t)(m0 + r) << 12) + (chunk << 5) + (c << 3);
            }
            const uint32_t sa = stg + r * PITCH + c * 16;
            cp_async16(sa, Ah + offA);
            cp_async16(sa + APART, Al + offA);
            cp_async16(sa + 2 * APART, B + ((size_t)(n0 + r) << 12) + (chunk << 5) + (c << 3));
        }
        cp_commit();
    };

    float acc[4][4][4];
#pragma unroll
    for (int fm = 0; fm < 4; fm++)
#pragma unroll
        for (int fn = 0; fn < 4; fn++)
#pragma unroll
            for (int j = 0; j < 4; j++) acc[fm][fn][j] = 0.f;

    load(0, 0);
    load(1, 1);

    const uint32_t aoff = (wm * 64 + (lane & 15)) * PITCH + (lane >> 4) * 16;
    const uint32_t boff = (wn * 32 + (lane & 15)) * PITCH + (lane >> 4) * 16;

    for (int c = 0; c < NCHUNK; c++) {
        const int st = c % NSTAGE;
        if (c < NCHUNK - 1) cp_wait<1>();
        else                cp_wait<0>();
        __syncthreads();  // data(c) ready AND all warps done with stage (c-1)%3
        if (c + 2 < NCHUNK) load(c + 2, (c + 2) % NSTAGE);

        const uint32_t stg = sb + st * STAGE_BYTES;
#pragma unroll
        for (int ks = 0; ks < 2; ks++) {
            uint32_t b[2][4];
#pragma unroll
            for (int fp = 0; fp < 2; fp++)
                ldsm_x4(b[fp][0], b[fp][1], b[fp][2], b[fp][3],
                        stg + 2 * APART + boff + fp * (16 * PITCH) + ks * 32);
#pragma unroll
            for (int fm = 0; fm < 4; fm++) {
                uint32_t a4[4];
                ldsm_x4(a4[0], a4[1], a4[2], a4[3],
                        stg + aoff + fm * (16 * PITCH) + ks * 32);
#pragma unroll
                for (int fn = 0; fn < 4; fn++)
                    mma16816(acc[fm][fn], a4, b[fn >> 1][fn & 1], b[fn >> 1][(fn & 1) + 2]);
                ldsm_x4(a4[0], a4[1], a4[2], a4[3],
                        stg + APART + aoff + fm * (16 * PITCH) + ks * 32);
#pragma unroll
                for (int fn = 0; fn < 4; fn++)
                    mma16816(acc[fm][fn], a4, b[fn >> 1][fn & 1], b[fn >> 1][(fn & 1) + 2]);
            }
        }
    }

    // epilogue
    float* outp = out + (size_t)SKIP * 1048576;
    const int rbase = m0 + wm * 64 + (lane >> 2);
    const int cbase = n0 + wn * 32 + (lane & 3) * 2;
#pragma unroll
    for (int fm = 0; fm < 4; fm++)
#pragma unroll
        for (int fn = 0; fn < 4; fn++) {
            const int rr = rbase + fm * 16;
            const int cc = cbase + fn * 8;
            *(float2*)(outp + (size_t)rr * 256 + cc) = make_float2(acc[fm][fn][0], acc[fm][fn][1]);
            *(float2*)(outp + (size_t)(rr + 8) * 256 + cc) = make_float2(acc[fm][fn][2], acc[fm][fn][3]);
        }
}

__global__ void __launch_bounds__(256, 2) gemm_kernel(float* __restrict__ out) {
    if (blockIdx.z == 0)      gemm_body<0>(out);
    else if (blockIdx.z == 1) gemm_body<1>(out);
    else                      gemm_body<2>(out);
}

// ----------------------------------------------------------------------------
extern "C" void kernel_launch(void* const* d_in, const int* in_sizes, int n_in,
                              void* d_out, int out_size) {
    const float* x  = (const float*)d_in[0];
    const float* c0 = (const float*)d_in[1];
    const float* c1 = (const float*)d_in[2];
    const float* c2 = (const float*)d_in[3];
    float* out = (float*)d_out;

    cudaFuncSetAttribute(gemm_kernel, cudaFuncAttributeMaxDynamicSharedMemorySize, SMEM_TOTAL);
    prep_kernel<<<dim3(64, 64), 256>>>(x);
    chain_kernel<<<dim3(64, 3), 256>>>(c0, c1, c2);
    gemm_kernel<<<dim3(32, 2, 3), 256, SMEM_TOTAL>>>(out);
}

// round 8
// speedup vs baseline: 3.4410x; 1.8396x over previous
#include <cuda_runtime.h>
#include <cuda_fp16.h>
#include <cstdint>

// ============================================================================
// node_s (4096x256) = X_s (4096x4096) @ C_s^T, single fp16 product
// (x->fp16 adds ~2.8e-4, C->fp16 adds ~2.1e-4; total ~3.5e-4 < 1e-3).
//   skip0: rows (b,n0), k=(n1,n2) -> X = x straight
//   skip1: rows (b,n1), k=(n0,n2) -> gather 64-row blocks (one b per CTA)
//   skip2: rows (b,n2), k=(n1,n0) -> X = x_T[b][n2][n1][n0]
// GEMM: CTA tile 64x128, grid 384 (all SMs), 128 thr (4 warps, 32x64 warp tile),
// 3-stage cp.async, one sync per chunk.
// ============================================================================

#define BM 64
#define BN 128
#define NCHUNK 128
#define PITCH 80                    // 32 fp16 = 64B + 16B pad: conflict-free ldsm
#define APART (BM * PITCH)          // 5120
#define STAGE_BYTES (APART + BN * PITCH)  // 15360: A | B
#define NSTAGE 3
#define SMEM_TOTAL (STAGE_BYTES * NSTAGE)  // 46080

// ---- scratch (device globals: no allocation) ----
__device__ __align__(1024) __half g_xh[16777216];   // [b][n0][n1][n2]
__device__ __align__(1024) __half g_xth[16777216];  // [b][n2][n1][n0]
__device__ __align__(1024) __half g_c[3u * 256 * 4096];  // chains [s][pq][k]

// ---- PTX helpers ----
__device__ __forceinline__ uint32_t smem_u32(const void* p) {
    uint32_t a;
    asm("{ .reg .u64 t; cvta.to.shared.u64 t, %1; cvt.u32.u64 %0, t; }" : "=r"(a) : "l"(p));
    return a;
}
__device__ __forceinline__ void cp_async16(uint32_t s, const void* g) {
    asm volatile("cp.async.cg.shared.global [%0], [%1], 16;\n" :: "r"(s), "l"(g));
}
__device__ __forceinline__ void cp_commit() { asm volatile("cp.async.commit_group;\n" ::: "memory"); }
template <int N> __device__ __forceinline__ void cp_wait() {
    asm volatile("cp.async.wait_group %0;\n" :: "n"(N) : "memory");
}
__device__ __forceinline__ void ldsm_x4(uint32_t& r0, uint32_t& r1, uint32_t& r2,
                                        uint32_t& r3, uint32_t addr) {
    asm volatile("ldmatrix.sync.aligned.m8n8.x4.shared.b16 {%0,%1,%2,%3}, [%4];"
                 : "=r"(r0), "=r"(r1), "=r"(r2), "=r"(r3) : "r"(addr));
}
__device__ __forceinline__ void mma16816(float* d, const uint32_t* a, uint32_t b0, uint32_t b1) {
    asm volatile("mma.sync.aligned.m16n8k16.row.col.f32.f16.f16.f32 "
                 "{%0,%1,%2,%3},{%4,%5,%6,%7},{%8,%9},{%0,%1,%2,%3};"
                 : "+f"(d[0]), "+f"(d[1]), "+f"(d[2]), "+f"(d[3])
                 : "r"(a[0]), "r"(a[1]), "r"(a[2]), "r"(a[3]), "r"(b0), "r"(b1));
}

// ============================================================================
// prep: x fp32 -> fp16 (hi only), straight + reversed. grid(64 n1, 64 b).
// ============================================================================
__global__ void __launch_bounds__(256) prep_kernel(const float* __restrict__ x) {
    __shared__ float tile[64][65];
    const int n1 = blockIdx.x, b = blockIdx.y, tid = threadIdx.x;
    const size_t base = (size_t)b * 262144 + (size_t)n1 * 64;
    const int r = tid >> 2, cs = (tid & 3) * 16;

#pragma unroll
    for (int j = 0; j < 4; j++) {
        float4 v = *(const float4*)(x + base + (size_t)r * 4096 + cs + j * 4);
        tile[r][cs + j * 4 + 0] = v.x;
        tile[r][cs + j * 4 + 1] = v.y;
        tile[r][cs + j * 4 + 2] = v.z;
        tile[r][cs + j * 4 + 3] = v.w;
    }
    __syncthreads();

    __half hb[16], hbt[16];
#pragma unroll
    for (int k = 0; k < 16; k++) {
        hb[k] = __float2half_rn(tile[r][cs + k]);   // straight [b][n0=r][n1][n2]
        hbt[k] = __float2half_rn(tile[cs + k][r]);  // reversed [b][n2=r][n1][n0]
    }
    const size_t o = base + (size_t)r * 4096 + cs;
#pragma unroll
    for (int j = 0; j < 2; j++) {
        *(float4*)(g_xh + o + j * 8)  = ((const float4*)hb)[j];
        *(float4*)(g_xth + o + j * 8) = ((const float4*)hbt)[j];
    }
}

// ============================================================================
// chain: C_s[pq][u*64+v] fp16. grid(64 u, 3 s), 256 thr = (p,q)
//   s0: u=n1,v=n2: core1[u][p][t]*core2[v][t][q]
//   s1: u=n0,v=n2: core2[v][p][t]*core0[u][t][q]
//   s2: u=n1,v=n0: core0[v][p][t]*core1[u][t][q]
// ============================================================================
__global__ void __launch_bounds__(256) chain_kernel(const float* __restrict__ c0,
                                                    const float* __restrict__ c1,
                                                    const float* __restrict__ c2) {
    const int u = blockIdx.x, s = blockIdx.y, tid = threadIdx.x;
    const int p = tid >> 4, q = tid & 15;
    __shared__ float U[256], V[256];
    const float* Uc = (s == 1) ? c0 : c1;
    const float* Vc = (s == 2) ? c0 : c2;
    U[tid] = Uc[u * 256 + tid];
    __syncthreads();
    float vals[64];
#pragma unroll
    for (int v = 0; v < 64; v++) {
        V[tid] = Vc[v * 256 + tid];
        __syncthreads();
        float acc = 0.f;
        if (s == 0) {
#pragma unroll
            for (int t = 0; t < 16; t++) acc += U[p * 16 + t] * V[t * 16 + q];
        } else {
#pragma unroll
            for (int t = 0; t < 16; t++) acc += V[p * 16 + t] * U[t * 16 + q];
        }
        vals[v] = acc;
        __syncthreads();
    }
    const size_t o = (size_t)s * 1048576 + (size_t)tid * 4096 + (size_t)u * 64;
#pragma unroll
    for (int v = 0; v < 64; v++) g_c[o + v] = __float2half_rn(vals[v]);
}

// ============================================================================
// GEMM: grid(64 m, 2 n, 3 skip), 128 threads (4 warps 2x2; warp tile 32x64).
// ============================================================================
template <int SKIP>
__device__ __forceinline__ void gemm_body(float* __restrict__ out) {
    extern __shared__ char smem[];
    const uint32_t sb = smem_u32(smem);
    const int tid = threadIdx.x, lane = tid & 31, wid = tid >> 5;
    const int wm = wid >> 1, wn = wid & 1;
    const int m0 = blockIdx.x * BM, n0 = blockIdx.y * BN;

    const __half* A = (SKIP == 2) ? g_xth : g_xh;
    const __half* B = g_c + (size_t)SKIP * 1048576;

    auto load = [&](int chunk, int st) {
        const uint32_t stg = sb + st * STAGE_BYTES;
        // A: 64 rows x 32 fp16 = 256 x 16B
#pragma unroll
        for (int i = 0; i < 2; i++) {
            const int lin = tid + i * 128;
            const int r = lin >> 2, c = lin & 3;
            size_t offA;
            if (SKIP == 1) {
                const int bb = m0 >> 6;  // one b per CTA (BM=64)
                offA = ((size_t)bb << 18) + ((size_t)(chunk >> 1) << 12) + (r << 6) +
                       ((chunk & 1) << 5) + (c << 3);
            } else {
                offA = ((size_t)(m0 + r) << 12) + (chunk << 5) + (c << 3);
            }
            cp_async16(stg + r * PITCH + c * 16, A + offA);
        }
        // B: 128 rows x 32 fp16 = 512 x 16B
#pragma unroll
        for (int i = 0; i < 4; i++) {
            const int lin = tid + i * 128;
            const int r = lin >> 2, c = lin & 3;
            cp_async16(stg + APART + r * PITCH + c * 16,
                       B + ((size_t)(n0 + r) << 12) + (chunk << 5) + (c << 3));
        }
        cp_commit();
    };

    float acc[2][8][4];
#pragma unroll
    for (int fm = 0; fm < 2; fm++)
#pragma unroll
        for (int fn = 0; fn < 8; fn++)
#pragma unroll
            for (int j = 0; j < 4; j++) acc[fm][fn][j] = 0.f;

    load(0, 0);
    load(1, 1);

    const uint32_t aoff = (wm * 32 + (lane & 15)) * PITCH + (lane >> 4) * 16;
    const uint32_t boff = APART + (wn * 64 + (lane & 15)) * PITCH + (lane >> 4) * 16;

    for (int c = 0; c < NCHUNK; c++) {
        const int st = c % NSTAGE;
        if (c < NCHUNK - 1) cp_wait<1>();
        else                cp_wait<0>();
        __syncthreads();  // data(c) ready AND all warps done with stage (c-1)%3
        if (c + 2 < NCHUNK) load(c + 2, (c + 2) % NSTAGE);

        const uint32_t stg = sb + st * STAGE_BYTES;
#pragma unroll
        for (int ks = 0; ks < 2; ks++) {
            uint32_t b[4][4];
#pragma unroll
            for (int fp = 0; fp < 4; fp++)
                ldsm_x4(b[fp][0], b[fp][1], b[fp][2], b[fp][3],
                        stg + boff + fp * (16 * PITCH) + ks * 32);
#pragma unroll
            for (int fm = 0; fm < 2; fm++) {
                uint32_t a4[4];
                ldsm_x4(a4[0], a4[1], a4[2], a4[3],
                        stg + aoff + fm * (16 * PITCH) + ks * 32);
#pragma unroll
                for (int fn = 0; fn < 8; fn++)
                    mma16816(acc[fm][fn], a4, b[fn >> 1][fn & 1], b[fn >> 1][(fn & 1) + 2]);
            }
        }
    }

    // epilogue
    float* outp = out + (size_t)SKIP * 1048576;
    const int rbase = m0 + wm * 32 + (lane >> 2);
    const int cbase = n0 + wn * 64 + (lane & 3) * 2;
#pragma unroll
    for (int fm = 0; fm < 2; fm++)
#pragma unroll
        for (int fn = 0; fn < 8; fn++) {
            const int rr = rbase + fm * 16;
            const int cc = cbase + fn * 8;
            *(float2*)(outp + (size_t)rr * 256 + cc) = make_float2(acc[fm][fn][0], acc[fm][fn][1]);
            *(float2*)(outp + (size_t)(rr + 8) * 256 + cc) = make_float2(acc[fm][fn][2], acc[fm][fn][3]);
        }
}

__global__ void __launch_bounds__(128, 4) gemm_kernel(float* __restrict__ out) {
    if (blockIdx.z == 0)      gemm_body<0>(out);
    else if (blockIdx.z == 1) gemm_body<1>(out);
    else                      gemm_body<2>(out);
}

// ----------------------------------------------------------------------------
extern "C" void kernel_launch(void* const* d_in, const int* in_sizes, int n_in,
                              void* d_out, int out_size) {
    const float* x  = (const float*)d_in[0];
    const float* c0 = (const float*)d_in[1];
    const float* c1 = (const float*)d_in[2];
    const float* c2 = (const float*)d_in[3];
    float* out = (float*)d_out;

    cudaFuncSetAttribute(gemm_kernel, cudaFuncAttributeMaxDynamicSharedMemorySize, SMEM_TOTAL);
    prep_kernel<<<dim3(64, 64), 256>>>(x);
    chain_kernel<<<dim3(64, 3), 256>>>(c0, c1, c2);
    gemm_kernel<<<dim3(64, 2, 3), 128, SMEM_TOTAL>>>(out);
}

// round 10
// speedup vs baseline: 3.5843x; 1.0416x over previous
#include <cuda_runtime.h>
#include <cuda_fp16.h>
#include <cstdint>

// ============================================================================
// node_s (4096x256) = X_s (4096x4096) @ C_s^T, single fp16 product.
//   skip0: rows (b,n0), k=(n1,n2) -> X = x straight
//   skip1: rows (b,n1), k=(n0,n2) -> gather 64-row blocks (one b per CTA)
//   skip2: rows (b,n2), k=(n1,n0) -> X = x_T[b][n2][n1][n0]
// GEMM: CTA tile 64x128, SPLIT-K x2 (768 CTAs) -> partials in g_part (plain
// stores, idempotent under graph-replay overlap), combine kernel sums halves.
// ============================================================================

#define BM 64
#define BN 128
#define KCHUNKS_HALF 64             // 2048 K per half, chunks of 32
#define PITCH 80                    // 32 fp16 = 64B + 16B pad: conflict-free ldsm
#define APART (BM * PITCH)          // 5120
#define STAGE_BYTES (APART + BN * PITCH)  // 15360: A | B
#define NSTAGE 3
#define SMEM_TOTAL (STAGE_BYTES * NSTAGE)  // 46080

// ---- scratch (device globals: no allocation) ----
__device__ __align__(1024) __half g_xh[16777216];   // [b][n0][n1][n2]
__device__ __align__(1024) __half g_xth[16777216];  // [b][n2][n1][n0]
__device__ __align__(1024) __half g_c[3u * 256 * 4096];  // chains [s][pq][k]
__device__ __align__(1024) float g_part[6u * 1048576];   // [khalf][skip][m][n]

// ---- PTX helpers ----
__device__ __forceinline__ uint32_t smem_u32(const void* p) {
    uint32_t a;
    asm("{ .reg .u64 t; cvta.to.shared.u64 t, %1; cvt.u32.u64 %0, t; }" : "=r"(a) : "l"(p));
    return a;
}
__device__ __forceinline__ void cp_async16(uint32_t s, const void* g) {
    asm volatile("cp.async.cg.shared.global [%0], [%1], 16;\n" :: "r"(s), "l"(g));
}
__device__ __forceinline__ void cp_commit() { asm volatile("cp.async.commit_group;\n" ::: "memory"); }
template <int N> __device__ __forceinline__ void cp_wait() {
    asm volatile("cp.async.wait_group %0;\n" :: "n"(N) : "memory");
}
__device__ __forceinline__ void ldsm_x4(uint32_t& r0, uint32_t& r1, uint32_t& r2,
                                        uint32_t& r3, uint32_t addr) {
    asm volatile("ldmatrix.sync.aligned.m8n8.x4.shared.b16 {%0,%1,%2,%3}, [%4];"
                 : "=r"(r0), "=r"(r1), "=r"(r2), "=r"(r3) : "r"(addr));
}
__device__ __forceinline__ void mma16816(float* d, const uint32_t* a, uint32_t b0, uint32_t b1) {
    asm volatile("mma.sync.aligned.m16n8k16.row.col.f32.f16.f16.f32 "
                 "{%0,%1,%2,%3},{%4,%5,%6,%7},{%8,%9},{%0,%1,%2,%3};"
                 : "+f"(d[0]), "+f"(d[1]), "+f"(d[2]), "+f"(d[3])
                 : "r"(a[0]), "r"(a[1]), "r"(a[2]), "r"(a[3]), "r"(b0), "r"(b1));
}

// ============================================================================
// prep: x fp32 -> fp16 (hi only), straight + reversed. grid(64 n1, 64 b).
// ============================================================================
__global__ void __launch_bounds__(256) prep_kernel(const float* __restrict__ x) {
    __shared__ float tile[64][65];
    const int n1 = blockIdx.x, b = blockIdx.y, tid = threadIdx.x;
    const size_t base = (size_t)b * 262144 + (size_t)n1 * 64;
    const int r = tid >> 2, cs = (tid & 3) * 16;

#pragma unroll
    for (int j = 0; j < 4; j++) {
        float4 v = *(const float4*)(x + base + (size_t)r * 4096 + cs + j * 4);
        tile[r][cs + j * 4 + 0] = v.x;
        tile[r][cs + j * 4 + 1] = v.y;
        tile[r][cs + j * 4 + 2] = v.z;
        tile[r][cs + j * 4 + 3] = v.w;
    }
    __syncthreads();

    __half hb[16], hbt[16];
#pragma unroll
    for (int k = 0; k < 16; k++) {
        hb[k] = __float2half_rn(tile[r][cs + k]);   // straight [b][n0=r][n1][n2]
        hbt[k] = __float2half_rn(tile[cs + k][r]);  // reversed [b][n2=r][n1][n0]
    }
    const size_t o = base + (size_t)r * 4096 + cs;
#pragma unroll
    for (int j = 0; j < 2; j++) {
        *(float4*)(g_xh + o + j * 8)  = ((const float4*)hb)[j];
        *(float4*)(g_xth + o + j * 8) = ((const float4*)hbt)[j];
    }
}

// ============================================================================
// chain: C_s[pq][u*64+v] fp16. grid(64 u, 3 s), 256 thr = (p,q)
//   s0: u=n1,v=n2: core1[u][p][t]*core2[v][t][q]
//   s1: u=n0,v=n2: core2[v][p][t]*core0[u][t][q]
//   s2: u=n1,v=n0: core0[v][p][t]*core1[u][t][q]
// ============================================================================
__global__ void __launch_bounds__(256) chain_kernel(const float* __restrict__ c0,
                                                    const float* __restrict__ c1,
                                                    const float* __restrict__ c2) {
    const int u = blockIdx.x, s = blockIdx.y, tid = threadIdx.x;
    const int p = tid >> 4, q = tid & 15;
    __shared__ float U[256], V[256];
    const float* Uc = (s == 1) ? c0 : c1;
    const float* Vc = (s == 2) ? c0 : c2;
    U[tid] = Uc[u * 256 + tid];
    __syncthreads();
    float vals[64];
#pragma unroll
    for (int v = 0; v < 64; v++) {
        V[tid] = Vc[v * 256 + tid];
        __syncthreads();
        float acc = 0.f;
        if (s == 0) {
#pragma unroll
            for (int t = 0; t < 16; t++) acc += U[p * 16 + t] * V[t * 16 + q];
        } else {
#pragma unroll
            for (int t = 0; t < 16; t++) acc += V[p * 16 + t] * U[t * 16 + q];
        }
        vals[v] = acc;
        __syncthreads();
    }
    const size_t o = (size_t)s * 1048576 + (size_t)tid * 4096 + (size_t)u * 64;
#pragma unroll
    for (int v = 0; v < 64; v++) g_c[o + v] = __float2half_rn(vals[v]);
}

// ============================================================================
// GEMM: grid(64 m, 2 n, 6 = skip*2 + khalf), 128 threads (4 warps 2x2,
// warp tile 32x64). Each CTA does K chunks [khalf*64, khalf*64+64) and writes
// its partial tile to g_part (plain stores).
// ============================================================================
template <int SKIP>
__device__ __forceinline__ void gemm_body(float* __restrict__ outp, int kbase) {
    extern __shared__ char smem[];
    const uint32_t sb = smem_u32(smem);
    const int tid = threadIdx.x, lane = tid & 31, wid = tid >> 5;
    const int wm = wid >> 1, wn = wid & 1;
    const int m0 = blockIdx.x * BM, n0 = blockIdx.y * BN;

    const __half* A = (SKIP == 2) ? g_xth : g_xh;
    const __half* B = g_c + (size_t)SKIP * 1048576;

    auto load = [&](int chunk, int st) {  // chunk: global index kbase..kbase+63
        const uint32_t stg = sb + st * STAGE_BYTES;
        // A: 64 rows x 32 fp16 = 256 x 16B
#pragma unroll
        for (int i = 0; i < 2; i++) {
            const int lin = tid + i * 128;
            const int r = lin >> 2, c = lin & 3;
            size_t offA;
            if (SKIP == 1) {
                const int bb = m0 >> 6;  // one b per CTA (BM=64)
                offA = ((size_t)bb << 18) + ((size_t)(chunk >> 1) << 12) + (r << 6) +
                       ((chunk & 1) << 5) + (c << 3);
            } else {
                offA = ((size_t)(m0 + r) << 12) + (chunk << 5) + (c << 3);
            }
            cp_async16(stg + r * PITCH + c * 16, A + offA);
        }
        // B: 128 rows x 32 fp16 = 512 x 16B
#pragma unroll
        for (int i = 0; i < 4; i++) {
            const int lin = tid + i * 128;
            const int r = lin >> 2, c = lin & 3;
            cp_async16(stg + APART + r * PITCH + c * 16,
                       B + ((size_t)(n0 + r) << 12) + (chunk << 5) + (c << 3));
        }
        cp_commit();
    };

    float acc[2][8][4];
#pragma unroll
    for (int fm = 0; fm < 2; fm++)
#pragma unroll
        for (int fn = 0; fn < 8; fn++)
#pragma unroll
            for (int j = 0; j < 4; j++) acc[fm][fn][j] = 0.f;

    load(kbase + 0, 0);
    load(kbase + 1, 1);

    const uint32_t aoff = (wm * 32 + (lane & 15)) * PITCH + (lane >> 4) * 16;
    const uint32_t boff = APART + (wn * 64 + (lane & 15)) * PITCH + (lane >> 4) * 16;

    for (int c = 0; c < KCHUNKS_HALF; c++) {
        const int st = c % NSTAGE;
        if (c < KCHUNKS_HALF - 1) cp_wait<1>();
        else                      cp_wait<0>();
        __syncthreads();  // data(c) ready AND all warps done with stage (c-1)%3
        if (c + 2 < KCHUNKS_HALF) load(kbase + c + 2, (c + 2) % NSTAGE);

        const uint32_t stg = sb + st * STAGE_BYTES;
#pragma unroll
        for (int ks = 0; ks < 2; ks++) {
            uint32_t b[4][4];
#pragma unroll
            for (int fp = 0; fp < 4; fp++)
                ldsm_x4(b[fp][0], b[fp][1], b[fp][2], b[fp][3],
                        stg + boff + fp * (16 * PITCH) + ks * 32);
#pragma unroll
            for (int fm = 0; fm < 2; fm++) {
                uint32_t a4[4];
                ldsm_x4(a4[0], a4[1], a4[2], a4[3],
                        stg + aoff + fm * (16 * PITCH) + ks * 32);
#pragma unroll
                for (int fn = 0; fn < 8; fn++)
                    mma16816(acc[fm][fn], a4, b[fn >> 1][fn & 1], b[fn >> 1][(fn & 1) + 2]);
            }
        }
    }

    // epilogue: plain stores of this half's partial (idempotent)
    const int rbase = m0 + wm * 32 + (lane >> 2);
    const int cbase = n0 + wn * 64 + (lane & 3) * 2;
#pragma unroll
    for (int fm = 0; fm < 2; fm++)
#pragma unroll
        for (int fn = 0; fn < 8; fn++) {
            const int rr = rbase + fm * 16;
            const int cc = cbase + fn * 8;
            *(float2*)(outp + (size_t)rr * 256 + cc) = make_float2(acc[fm][fn][0], acc[fm][fn][1]);
            *(float2*)(outp + (size_t)(rr + 8) * 256 + cc) = make_float2(acc[fm][fn][2], acc[fm][fn][3]);
        }
}

__global__ void __launch_bounds__(128, 4) gemm_kernel() {
    const int skip = blockIdx.z >> 1;
    const int khalf = blockIdx.z & 1;
    float* outp = g_part + ((size_t)khalf * 3 + skip) * 1048576;
    const int kbase = khalf * KCHUNKS_HALF;
    if (skip == 0)      gemm_body<0>(outp, kbase);
    else if (skip == 1) gemm_body<1>(outp, kbase);
    else                gemm_body<2>(outp, kbase);
}

// ============================================================================
// combine: out = part0 + part1. 3x1048576 floats, float4. grid 3072 x 256.
// ============================================================================
__global__ void __launch_bounds__(256) combine_kernel(float* __restrict__ out) {
    const size_t i = ((size_t)blockIdx.x * 256 + threadIdx.x) * 4;
    float4 a = *(const float4*)(g_part + i);
    float4 b = *(const float4*)(g_part + 3u * 1048576 + i);
    *(float4*)(out + i) = make_float4(a.x + b.x, a.y + b.y, a.z + b.z, a.w + b.w);
}

// ----------------------------------------------------------------------------
extern "C" void kernel_launch(void* const* d_in, const int* in_sizes, int n_in,
                              void* d_out, int out_size) {
    const float* x  = (const float*)d_in[0];
    const float* c0 = (const float*)d_in[1];
    const float* c1 = (const float*)d_in[2];
    const float* c2 = (const float*)d_in[3];
    float* out = (float*)d_out;

    cudaFuncSetAttribute(gemm_kernel, cudaFuncAttributeMaxDynamicSharedMemorySize, SMEM_TOTAL);
    prep_kernel<<<dim3(64, 64), 256>>>(x);
    chain_kernel<<<dim3(64, 3), 256>>>(c0, c1, c2);
    gemm_kernel<<<dim3(64, 2, 6), 128, SMEM_TOTAL>>>();
    combine_kernel<<<3072, 256>>>(out);
}

// round 11
// speedup vs baseline: 3.6718x; 1.0244x over previous
#include <cuda_runtime.h>
#include <cuda_fp16.h>
#include <cstdint>

// ============================================================================
// node_s (4096x256) = X_s (4096x4096) @ C_s^T, single fp16 product.
//   skip0: rows (b,n0), k=(n1,n2) -> X = x straight
//   skip1: rows (b,n1), k=(n0,n2) -> gather 64-row blocks (one b per CTA)
//   skip2: rows (b,n2), k=(n1,n0) -> X = x_T[b][n2][n1][n0]
// GEMM: CTA tile 64x128, SPLIT-K x4 (1536 CTAs, wave tail 1.06) -> partials in
// g_part (plain stores, replay-idempotent), combine sums 4 quarters.
// prep+chain fused into one launch (concurrent blocks).
// ============================================================================

#define BM 64
#define BN 128
#define KCHUNKS_QTR 32              // 1024 K per quarter, chunks of 32
#define PITCH 80                    // 32 fp16 = 64B + 16B pad: conflict-free ldsm
#define APART (BM * PITCH)          // 5120
#define STAGE_BYTES (APART + BN * PITCH)  // 15360: A | B
#define NSTAGE 3
#define SMEM_TOTAL (STAGE_BYTES * NSTAGE)  // 46080

// ---- scratch (device globals: no allocation) ----
__device__ __align__(1024) __half g_xh[16777216];   // [b][n0][n1][n2]
__device__ __align__(1024) __half g_xth[16777216];  // [b][n2][n1][n0]
__device__ __align__(1024) __half g_c[3u * 256 * 4096];  // chains [s][pq][k]
__device__ __align__(1024) float g_part[4u * 3145728];   // [kq][skip][m][n]

// ---- PTX helpers ----
__device__ __forceinline__ uint32_t smem_u32(const void* p) {
    uint32_t a;
    asm("{ .reg .u64 t; cvta.to.shared.u64 t, %1; cvt.u32.u64 %0, t; }" : "=r"(a) : "l"(p));
    return a;
}
__device__ __forceinline__ void cp_async16(uint32_t s, const void* g) {
    asm volatile("cp.async.cg.shared.global [%0], [%1], 16;\n" :: "r"(s), "l"(g));
}
__device__ __forceinline__ void cp_commit() { asm volatile("cp.async.commit_group;\n" ::: "memory"); }
template <int N> __device__ __forceinline__ void cp_wait() {
    asm volatile("cp.async.wait_group %0;\n" :: "n"(N) : "memory");
}
__device__ __forceinline__ void ldsm_x4(uint32_t& r0, uint32_t& r1, uint32_t& r2,
                                        uint32_t& r3, uint32_t addr) {
    asm volatile("ldmatrix.sync.aligned.m8n8.x4.shared.b16 {%0,%1,%2,%3}, [%4];"
                 : "=r"(r0), "=r"(r1), "=r"(r2), "=r"(r3) : "r"(addr));
}
__device__ __forceinline__ void mma16816(float* d, const uint32_t* a, uint32_t b0, uint32_t b1) {
    asm volatile("mma.sync.aligned.m16n8k16.row.col.f32.f16.f16.f32 "
                 "{%0,%1,%2,%3},{%4,%5,%6,%7},{%8,%9},{%0,%1,%2,%3};"
                 : "+f"(d[0]), "+f"(d[1]), "+f"(d[2]), "+f"(d[3])
                 : "r"(a[0]), "r"(a[1]), "r"(a[2]), "r"(a[3]), "r"(b0), "r"(b1));
}

// ============================================================================
// prep+chain fused. grid(64, 67): y<64 -> prep tile (n1=y, b=x);
//                                  y>=64 -> chain (u=x, s=y-64). 256 threads.
// ============================================================================
__global__ void __launch_bounds__(256) prep_chain_kernel(const float* __restrict__ x,
                                                         const float* __restrict__ c0,
                                                         const float* __restrict__ c1,
                                                         const float* __restrict__ c2) {
    __shared__ float tile[64][65];  // prep use; chain uses first 512 floats
    const int tid = threadIdx.x;

    if (blockIdx.y < 64) {
        // ---- prep: x fp32 -> fp16, straight + reversed ----
        const int n1 = blockIdx.y, b = blockIdx.x;
        const size_t base = (size_t)b * 262144 + (size_t)n1 * 64;
        const int r = tid >> 2, cs = (tid & 3) * 16;

        float v[16];
#pragma unroll
        for (int j = 0; j < 4; j++) {
            float4 q = *(const float4*)(x + base + (size_t)r * 4096 + cs + j * 4);
            v[j * 4 + 0] = q.x; v[j * 4 + 1] = q.y; v[j * 4 + 2] = q.z; v[j * 4 + 3] = q.w;
        }
        // straight [b][n0=r][n1][n2=cs+k]: convert directly from regs
        __half hb[16];
#pragma unroll
        for (int k = 0; k < 16; k++) hb[k] = __float2half_rn(v[k]);
        const size_t o = base + (size_t)r * 4096 + cs;
        *(float4*)(g_xh + o) = ((const float4*)hb)[0];
        *(float4*)(g_xh + o + 8) = ((const float4*)hb)[1];
        // stage for transpose
#pragma unroll
        for (int k = 0; k < 16; k++) tile[r][cs + k] = v[k];
        __syncthreads();
        // reversed [b][n2=r][n1][n0=cs+k]
        __half hbt[16];
#pragma unroll
        for (int k = 0; k < 16; k++) hbt[k] = __float2half_rn(tile[cs + k][r]);
        *(float4*)(g_xth + o) = ((const float4*)hbt)[0];
        *(float4*)(g_xth + o + 8) = ((const float4*)hbt)[1];
    } else {
        // ---- chain: C_s[pq][u*64+v] fp16 ----
        //   s0: u=n1,v=n2: core1[u][p][t]*core2[v][t][q]
        //   s1: u=n0,v=n2: core2[v][p][t]*core0[u][t][q]
        //   s2: u=n1,v=n0: core0[v][p][t]*core1[u][t][q]
        const int u = blockIdx.x, s = blockIdx.y - 64;
        const int p = tid >> 4, q = tid & 15;
        float* U = &tile[0][0];
        float* V = &tile[8][0];  // disjoint 256-float regions
        const float* Uc = (s == 1) ? c0 : c1;
        const float* Vc = (s == 2) ? c0 : c2;
        U[tid] = Uc[u * 256 + tid];
        __syncthreads();
        float vals[64];
#pragma unroll
        for (int v2 = 0; v2 < 64; v2++) {
            V[tid] = Vc[v2 * 256 + tid];
            __syncthreads();
            float acc = 0.f;
            if (s == 0) {
#pragma unroll
                for (int t = 0; t < 16; t++) acc += U[p * 16 + t] * V[t * 16 + q];
            } else {
#pragma unroll
                for (int t = 0; t < 16; t++) acc += V[p * 16 + t] * U[t * 16 + q];
            }
            vals[v2] = acc;
            __syncthreads();
        }
        const size_t o = (size_t)s * 1048576 + (size_t)tid * 4096 + (size_t)u * 64;
#pragma unroll
        for (int v2 = 0; v2 < 64; v2++) g_c[o + v2] = __float2half_rn(vals[v2]);
    }
}

// ============================================================================
// GEMM: grid(64 m, 2 n, 12 = skip*4 + kq), 128 threads (4 warps 2x2, warp tile
// 32x64). Each CTA does K chunks [kq*32, kq*32+32), partial -> g_part.
// ============================================================================
template <int SKIP>
__device__ __forceinline__ void gemm_body(float* __restrict__ outp, int kbase) {
    extern __shared__ char smem[];
    const uint32_t sb = smem_u32(smem);
    const int tid = threadIdx.x, lane = tid & 31, wid = tid >> 5;
    const int wm = wid >> 1, wn = wid & 1;
    const int m0 = blockIdx.x * BM, n0 = blockIdx.y * BN;

    const __half* A = (SKIP == 2) ? g_xth : g_xh;
    const __half* B = g_c + (size_t)SKIP * 1048576;

    auto load = [&](int chunk, int st) {  // chunk: global 0..127
        const uint32_t stg = sb + st * STAGE_BYTES;
#pragma unroll
        for (int i = 0; i < 2; i++) {
            const int lin = tid + i * 128;
            const int r = lin >> 2, c = lin & 3;
            size_t offA;
            if (SKIP == 1) {
                const int bb = m0 >> 6;  // one b per CTA (BM=64)
                offA = ((size_t)bb << 18) + ((size_t)(chunk >> 1) << 12) + (r << 6) +
                       ((chunk & 1) << 5) + (c << 3);
            } else {
                offA = ((size_t)(m0 + r) << 12) + (chunk << 5) + (c << 3);
            }
            cp_async16(stg + r * PITCH + c * 16, A + offA);
        }
#pragma unroll
        for (int i = 0; i < 4; i++) {
            const int lin = tid + i * 128;
            const int r = lin >> 2, c = lin & 3;
            cp_async16(stg + APART + r * PITCH + c * 16,
                       B + ((size_t)(n0 + r) << 12) + (chunk << 5) + (c << 3));
        }
        cp_commit();
    };

    float acc[2][8][4];
#pragma unroll
    for (int fm = 0; fm < 2; fm++)
#pragma unroll
        for (int fn = 0; fn < 8; fn++)
#pragma unroll
            for (int j = 0; j < 4; j++) acc[fm][fn][j] = 0.f;

    load(kbase + 0, 0);
    load(kbase + 1, 1);

    const uint32_t aoff = (wm * 32 + (lane & 15)) * PITCH + (lane >> 4) * 16;
    const uint32_t boff = APART + (wn * 64 + (lane & 15)) * PITCH + (lane >> 4) * 16;

    for (int c = 0; c < KCHUNKS_QTR; c++) {
        const int st = c % NSTAGE;
        if (c < KCHUNKS_QTR - 1) cp_wait<1>();
        else                     cp_wait<0>();
        __syncthreads();
        if (c + 2 < KCHUNKS_QTR) load(kbase + c + 2, (c + 2) % NSTAGE);

        const uint32_t stg = sb + st * STAGE_BYTES;
#pragma unroll
        for (int ks = 0; ks < 2; ks++) {
            uint32_t b[4][4];
#pragma unroll
            for (int fp = 0; fp < 4; fp++)
                ldsm_x4(b[fp][0], b[fp][1], b[fp][2], b[fp][3],
                        stg + boff + fp * (16 * PITCH) + ks * 32);
#pragma unroll
            for (int fm = 0; fm < 2; fm++) {
                uint32_t a4[4];
                ldsm_x4(a4[0], a4[1], a4[2], a4[3],
                        stg + aoff + fm * (16 * PITCH) + ks * 32);
#pragma unroll
                for (int fn = 0; fn < 8; fn++)
                    mma16816(acc[fm][fn], a4, b[fn >> 1][fn & 1], b[fn >> 1][(fn & 1) + 2]);
            }
        }
    }

    // epilogue: plain stores of this quarter's partial (idempotent)
    const int rbase = m0 + wm * 32 + (lane >> 2);
    const int cbase = n0 + wn * 64 + (lane & 3) * 2;
#pragma unroll
    for (int fm = 0; fm < 2; fm++)
#pragma unroll
        for (int fn = 0; fn < 8; fn++) {
            const int rr = rbase + fm * 16;
            const int cc = cbase + fn * 8;
            *(float2*)(outp + (size_t)rr * 256 + cc) = make_float2(acc[fm][fn][0], acc[fm][fn][1]);
            *(float2*)(outp + (size_t)(rr + 8) * 256 + cc) = make_float2(acc[fm][fn][2], acc[fm][fn][3]);
        }
}

__global__ void __launch_bounds__(128, 4) gemm_kernel() {
    const int skip = blockIdx.z >> 2;
    const int kq = blockIdx.z & 3;
    float* outp = g_part + (size_t)kq * 3145728 + (size_t)skip * 1048576;
    const int kbase = kq * KCHUNKS_QTR;
    if (skip == 0)      gemm_body<0>(outp, kbase);
    else if (skip == 1) gemm_body<1>(outp, kbase);
    else                gemm_body<2>(outp, kbase);
}

// ============================================================================
// combine: out[j] = sum_kq g_part[kq][j]. 3145728 floats, 8 per thread.
// grid 1536 x 256.
// ============================================================================
__global__ void __launch_bounds__(256) combine_kernel(float* __restrict__ out) {
    const size_t i = ((size_t)blockIdx.x * 256 + threadIdx.x) * 8;
#pragma unroll
    for (int h = 0; h < 2; h++) {
        const size_t j = i + h * 4;
        float4 a = *(const float4*)(g_part + j);
        float4 b = *(const float4*)(g_part + 3145728 + j);
        float4 c = *(const float4*)(g_part + 2u * 3145728 + j);
        float4 d = *(const float4*)(g_part + 3u * 3145728 + j);
        *(float4*)(out + j) = make_float4((a.x + b.x) + (c.x + d.x),
                                          (a.y + b.y) + (c.y + d.y),
                                          (a.z + b.z) + (c.z + d.z),
                                          (a.w + b.w) + (c.w + d.w));
    }
}

// ----------------------------------------------------------------------------
extern "C" void kernel_launch(void* const* d_in, const int* in_sizes, int n_in,
                              void* d_out, int out_size) {
    const float* x  = (const float*)d_in[0];
    const float* c0 = (const float*)d_in[1];
    const float* c1 = (const float*)d_in[2];
    const float* c2 = (const float*)d_in[3];
    float* out = (float*)d_out;

    cudaFuncSetAttribute(gemm_kernel, cudaFuncAttributeMaxDynamicSharedMemorySize, SMEM_TOTAL);
    prep_chain_kernel<<<dim3(64, 67), 256>>>(x, c0, c1, c2);
    gemm_kernel<<<dim3(64, 2, 12), 128, SMEM_TOTAL>>>();
    combine_kernel<<<1536, 256>>>(out);
}

// round 12
// speedup vs baseline: 3.7141x; 1.0115x over previous
#include <cuda_runtime.h>
#include <cuda_fp16.h>
#include <cstdint>

// ============================================================================
// node_s (4096x256) = X_s (4096x4096) @ C_s^T, single fp16 product.
//   skip0: rows (b,n0), k=(n1,n2) -> X = x straight
//   skip1: rows (b,n1), k=(n0,n2) -> gather 64-row blocks (one b per CTA)
//   skip2: rows (b,n2), k=(n1,n0) -> X = x_T[b][n2][n1][n0]
// GEMM: CTA tile 64x128, SPLIT-K x4 (1536 CTAs) -> partials in g_part (plain
// stores, replay-idempotent), combine sums 4 quarters.
// prep and chain are SEPARATE kernels (fusion caused spill in chain branch).
// ============================================================================

#define BM 64
#define BN 128
#define KCHUNKS_QTR 32              // 1024 K per quarter, chunks of 32
#define PITCH 80                    // 32 fp16 = 64B + 16B pad: conflict-free ldsm
#define APART (BM * PITCH)          // 5120
#define STAGE_BYTES (APART + BN * PITCH)  // 15360: A | B
#define NSTAGE 3
#define SMEM_TOTAL (STAGE_BYTES * NSTAGE)  // 46080

// ---- scratch (device globals: no allocation) ----
__device__ __align__(1024) __half g_xh[16777216];   // [b][n0][n1][n2]
__device__ __align__(1024) __half g_xth[16777216];  // [b][n2][n1][n0]
__device__ __align__(1024) __half g_c[3u * 256 * 4096];  // chains [s][pq][k]
__device__ __align__(1024) float g_part[4u * 3145728];   // [kq][skip][m][n]

// ---- PTX helpers ----
__device__ __forceinline__ uint32_t smem_u32(const void* p) {
    uint32_t a;
    asm("{ .reg .u64 t; cvta.to.shared.u64 t, %1; cvt.u32.u64 %0, t; }" : "=r"(a) : "l"(p));
    return a;
}
__device__ __forceinline__ void cp_async16(uint32_t s, const void* g) {
    asm volatile("cp.async.cg.shared.global [%0], [%1], 16;\n" :: "r"(s), "l"(g));
}
__device__ __forceinline__ void cp_commit() { asm volatile("cp.async.commit_group;\n" ::: "memory"); }
template <int N> __device__ __forceinline__ void cp_wait() {
    asm volatile("cp.async.wait_group %0;\n" :: "n"(N) : "memory");
}
__device__ __forceinline__ void ldsm_x4(uint32_t& r0, uint32_t& r1, uint32_t& r2,
                                        uint32_t& r3, uint32_t addr) {
    asm volatile("ldmatrix.sync.aligned.m8n8.x4.shared.b16 {%0,%1,%2,%3}, [%4];"
                 : "=r"(r0), "=r"(r1), "=r"(r2), "=r"(r3) : "r"(addr));
}
__device__ __forceinline__ void mma16816(float* d, const uint32_t* a, uint32_t b0, uint32_t b1) {
    asm volatile("mma.sync.aligned.m16n8k16.row.col.f32.f16.f16.f32 "
                 "{%0,%1,%2,%3},{%4,%5,%6,%7},{%8,%9},{%0,%1,%2,%3};"
                 : "+f"(d[0]), "+f"(d[1]), "+f"(d[2]), "+f"(d[3])
                 : "r"(a[0]), "r"(a[1]), "r"(a[2]), "r"(a[3]), "r"(b0), "r"(b1));
}

// ============================================================================
// prep: x fp32 -> fp16, straight [b][n0][n1][n2] + reversed [b][n2][n1][n0].
// grid(64 n1, 64 b), 256 threads. Straight converted from load regs.
// ============================================================================
__global__ void __launch_bounds__(256) prep_kernel(const float* __restrict__ x) {
    __shared__ float tile[64][65];
    const int n1 = blockIdx.x, b = blockIdx.y, tid = threadIdx.x;
    const size_t base = (size_t)b * 262144 + (size_t)n1 * 64;
    const int r = tid >> 2, cs = (tid & 3) * 16;

    float v[16];
#pragma unroll
    for (int j = 0; j < 4; j++) {
        float4 q = *(const float4*)(x + base + (size_t)r * 4096 + cs + j * 4);
        v[j * 4 + 0] = q.x; v[j * 4 + 1] = q.y; v[j * 4 + 2] = q.z; v[j * 4 + 3] = q.w;
    }
    __half hb[16];
#pragma unroll
    for (int k = 0; k < 16; k++) hb[k] = __float2half_rn(v[k]);
    const size_t o = base + (size_t)r * 4096 + cs;
    *(float4*)(g_xh + o) = ((const float4*)hb)[0];
    *(float4*)(g_xh + o + 8) = ((const float4*)hb)[1];

#pragma unroll
    for (int k = 0; k < 16; k++) tile[r][cs + k] = v[k];
    __syncthreads();

    __half hbt[16];
#pragma unroll
    for (int k = 0; k < 16; k++) hbt[k] = __float2half_rn(tile[cs + k][r]);
    *(float4*)(g_xth + o) = ((const float4*)hbt)[0];
    *(float4*)(g_xth + o + 8) = ((const float4*)hbt)[1];
}

// ============================================================================
// chain: C_s[pq][u*64+v] fp16. grid(64 u, 3 s), 256 thr = (p,q)
//   s0: u=n1,v=n2: core1[u][p][t]*core2[v][t][q]
//   s1: u=n0,v=n2: core2[v][p][t]*core0[u][t][q]
//   s2: u=n1,v=n0: core0[v][p][t]*core1[u][t][q]
// ============================================================================
__global__ void __launch_bounds__(256) chain_kernel(const float* __restrict__ c0,
                                                    const float* __restrict__ c1,
                                                    const float* __restrict__ c2) {
    const int u = blockIdx.x, s = blockIdx.y, tid = threadIdx.x;
    const int p = tid >> 4, q = tid & 15;
    __shared__ float U[256], V[256];
    const float* Uc = (s == 1) ? c0 : c1;
    const float* Vc = (s == 2) ? c0 : c2;
    U[tid] = Uc[u * 256 + tid];
    __syncthreads();
    float vals[64];
#pragma unroll
    for (int v = 0; v < 64; v++) {
        V[tid] = Vc[v * 256 + tid];
        __syncthreads();
        float acc = 0.f;
        if (s == 0) {
#pragma unroll
            for (int t = 0; t < 16; t++) acc += U[p * 16 + t] * V[t * 16 + q];
        } else {
#pragma unroll
            for (int t = 0; t < 16; t++) acc += V[p * 16 + t] * U[t * 16 + q];
        }
        vals[v] = acc;
        __syncthreads();
    }
    const size_t o = (size_t)s * 1048576 + (size_t)tid * 4096 + (size_t)u * 64;
#pragma unroll
    for (int v = 0; v < 64; v++) g_c[o + v] = __float2half_rn(vals[v]);
}

// ============================================================================
// GEMM: grid(64 m, 2 n, 12 = skip*4 + kq), 128 threads (4 warps 2x2, warp tile
// 32x64). Each CTA does K chunks [kq*32, kq*32+32), partial -> g_part.
// ============================================================================
template <int SKIP>
__device__ __forceinline__ void gemm_body(float* __restrict__ outp, int kbase) {
    extern __shared__ char smem[];
    const uint32_t sb = smem_u32(smem);
    const int tid = threadIdx.x, lane = tid & 31, wid = tid >> 5;
    const int wm = wid >> 1, wn = wid & 1;
    const int m0 = blockIdx.x * BM, n0 = blockIdx.y * BN;

    const __half* A = (SKIP == 2) ? g_xth : g_xh;
    const __half* B = g_c + (size_t)SKIP * 1048576;

    auto load = [&](int chunk, int st) {  // chunk: global 0..127
        const uint32_t stg = sb + st * STAGE_BYTES;
#pragma unroll
        for (int i = 0; i < 2; i++) {
            const int lin = tid + i * 128;
            const int r = lin >> 2, c = lin & 3;
            size_t offA;
            if (SKIP == 1) {
                const int bb = m0 >> 6;  // one b per CTA (BM=64)
                offA = ((size_t)bb << 18) + ((size_t)(chunk >> 1) << 12) + (r << 6) +
                       ((chunk & 1) << 5) + (c << 3);
            } else {
                offA = ((size_t)(m0 + r) << 12) + (chunk << 5) + (c << 3);
            }
            cp_async16(stg + r * PITCH + c * 16, A + offA);
        }
#pragma unroll
        for (int i = 0; i < 4; i++) {
            const int lin = tid + i * 128;
            const int r = lin >> 2, c = lin & 3;
            cp_async16(stg + APART + r * PITCH + c * 16,
                       B + ((size_t)(n0 + r) << 12) + (chunk << 5) + (c << 3));
        }
        cp_commit();
    };

    float acc[2][8][4];
#pragma unroll
    for (int fm = 0; fm < 2; fm++)
#pragma unroll
        for (int fn = 0; fn < 8; fn++)
#pragma unroll
            for (int j = 0; j < 4; j++) acc[fm][fn][j] = 0.f;

    load(kbase + 0, 0);
    load(kbase + 1, 1);

    const uint32_t aoff = (wm * 32 + (lane & 15)) * PITCH + (lane >> 4) * 16;
    const uint32_t boff = APART + (wn * 64 + (lane & 15)) * PITCH + (lane >> 4) * 16;

    for (int c = 0; c < KCHUNKS_QTR; c++) {
        const int st = c % NSTAGE;
        if (c < KCHUNKS_QTR - 1) cp_wait<1>();
        else                     cp_wait<0>();
        __syncthreads();
        if (c + 2 < KCHUNKS_QTR) load(kbase + c + 2, (c + 2) % NSTAGE);

        const uint32_t stg = sb + st * STAGE_BYTES;
#pragma unroll
        for (int ks = 0; ks < 2; ks++) {
            uint32_t b[4][4];
#pragma unroll
            for (int fp = 0; fp < 4; fp++)
                ldsm_x4(b[fp][0], b[fp][1], b[fp][2], b[fp][3],
                        stg + boff + fp * (16 * PITCH) + ks * 32);
#pragma unroll
            for (int fm = 0; fm < 2; fm++) {
                uint32_t a4[4];
                ldsm_x4(a4[0], a4[1], a4[2], a4[3],
                        stg + aoff + fm * (16 * PITCH) + ks * 32);
#pragma unroll
                for (int fn = 0; fn < 8; fn++)
                    mma16816(acc[fm][fn], a4, b[fn >> 1][fn & 1], b[fn >> 1][(fn & 1) + 2]);
            }
        }
    }

    // epilogue: plain stores of this quarter's partial (idempotent)
    const int rbase = m0 + wm * 32 + (lane >> 2);
    const int cbase = n0 + wn * 64 + (lane & 3) * 2;
#pragma unroll
    for (int fm = 0; fm < 2; fm++)
#pragma unroll
        for (int fn = 0; fn < 8; fn++) {
            const int rr = rbase + fm * 16;
            const int cc = cbase + fn * 8;
            *(float2*)(outp + (size_t)rr * 256 + cc) = make_float2(acc[fm][fn][0], acc[fm][fn][1]);
            *(float2*)(outp + (size_t)(rr + 8) * 256 + cc) = make_float2(acc[fm][fn][2], acc[fm][fn][3]);
        }
}

__global__ void __launch_bounds__(128, 4) gemm_kernel() {
    const int skip = blockIdx.z >> 2;
    const int kq = blockIdx.z & 3;
    float* outp = g_part + (size_t)kq * 3145728 + (size_t)skip * 1048576;
    const int kbase = kq * KCHUNKS_QTR;
    if (skip == 0)      gemm_body<0>(outp, kbase);
    else if (skip == 1) gemm_body<1>(outp, kbase);
    else                gemm_body<2>(outp, kbase);
}

// ============================================================================
// combine: out[j] = sum_kq g_part[kq][j]. 3145728 floats, 8 per thread.
// grid 1536 x 256.
// ============================================================================
__global__ void __launch_bounds__(256) combine_kernel(float* __restrict__ out) {
    const size_t i = ((size_t)blockIdx.x * 256 + threadIdx.x) * 8;
#pragma unroll
    for (int h = 0; h < 2; h++) {
        const size_t j = i + h * 4;
        float4 a = *(const float4*)(g_part + j);
        float4 b = *(const float4*)(g_part + 3145728 + j);
        float4 c = *(const float4*)(g_part + 2u * 3145728 + j);
        float4 d = *(const float4*)(g_part + 3u * 3145728 + j);
        *(float4*)(out + j) = make_float4((a.x + b.x) + (c.x + d.x),
                                          (a.y + b.y) + (c.y + d.y),
                                          (a.z + b.z) + (c.z + d.z),
                                          (a.w + b.w) + (c.w + d.w));
    }
}

// ----------------------------------------------------------------------------
extern "C" void kernel_launch(void* const* d_in, const int* in_sizes, int n_in,
                              void* d_out, int out_size) {
    const float* x  = (const float*)d_in[0];
    const float* c0 = (const float*)d_in[1];
    const float* c1 = (const float*)d_in[2];
    const float* c2 = (const float*)d_in[3];
    float* out = (float*)d_out;

    cudaFuncSetAttribute(gemm_kernel, cudaFuncAttributeMaxDynamicSharedMemorySize, SMEM_TOTAL);
    chain_kernel<<<dim3(64, 3), 256>>>(c0, c1, c2);
    prep_kernel<<<dim3(64, 64), 256>>>(x);
    gemm_kernel<<<dim3(64, 2, 12), 128, SMEM_TOTAL>>>();
    combine_kernel<<<1536, 256>>>(out);
}

// round 13
// speedup vs baseline: 3.7568x; 1.0115x over previous
#include <cuda_runtime.h>
#include <cuda_fp16.h>
#include <cstdint>

// ============================================================================
// node_s (4096x256) = X_s (4096x4096) @ C_s^T, single fp16 product.
//   skip0: rows (b,n0), k=(n1,n2) -> A rows from g_xh straight
//   skip1: rows (b,n1), k=(n0,n2) -> gather 64-row blocks of g_xh
//   skip2: rows (b,n2), k=(n1,n0) -> A^T tiles from g_xh + ldmatrix.trans
// SPLIT-K x4 (1536 CTAs); partials in g_part; 4th-arriving CTA per tile
// (threadfence+ticket) sums partials -> out. No combine kernel, no g_xth.
// ============================================================================

#define BM 64
#define BN 128
#define KCHUNKS_QTR 32              // 1024 K per quarter, chunks of 32
#define PITCH 80                    // B/A rows: 64B + 16B pad
#define TPITCH 144                  // skip2 A^T rows: 128B + 16B pad
#define APART (BM * PITCH)          // 5120 (skip2 uses 32*144=4608 of it)
#define STAGE_BYTES (APART + BN * PITCH)  // 15360
#define NSTAGE 3
#define SMEM_TOTAL (STAGE_BYTES * NSTAGE)  // 46080

// ---- scratch (device globals: no allocation) ----
__device__ __align__(1024) __half g_xh[16777216];        // [b][n0][n1][n2]
__device__ __align__(1024) __half g_c[3u * 256 * 4096];  // chains [s][pq][k]
__device__ __align__(1024) float g_part[4u * 3145728];   // [kq][skip][m][n]
__device__ unsigned int g_ticket[384];                   // [skip][mtile][ntile]

// ---- PTX helpers ----
__device__ __forceinline__ uint32_t smem_u32(const void* p) {
    uint32_t a;
    asm("{ .reg .u64 t; cvta.to.shared.u64 t, %1; cvt.u32.u64 %0, t; }" : "=r"(a) : "l"(p));
    return a;
}
__device__ __forceinline__ void cp_async16(uint32_t s, const void* g) {
    asm volatile("cp.async.cg.shared.global [%0], [%1], 16;\n" :: "r"(s), "l"(g));
}
__device__ __forceinline__ void cp_commit() { asm volatile("cp.async.commit_group;\n" ::: "memory"); }
template <int N> __device__ __forceinline__ void cp_wait() {
    asm volatile("cp.async.wait_group %0;\n" :: "n"(N) : "memory");
}
__device__ __forceinline__ void ldsm_x4(uint32_t& r0, uint32_t& r1, uint32_t& r2,
                                        uint32_t& r3, uint32_t addr) {
    asm volatile("ldmatrix.sync.aligned.m8n8.x4.shared.b16 {%0,%1,%2,%3}, [%4];"
                 : "=r"(r0), "=r"(r1), "=r"(r2), "=r"(r3) : "r"(addr));
}
__device__ __forceinline__ void ldsm_x4_t(uint32_t& r0, uint32_t& r1, uint32_t& r2,
                                          uint32_t& r3, uint32_t addr) {
    asm volatile("ldmatrix.sync.aligned.m8n8.x4.trans.shared.b16 {%0,%1,%2,%3}, [%4];"
                 : "=r"(r0), "=r"(r1), "=r"(r2), "=r"(r3) : "r"(addr));
}
__device__ __forceinline__ void mma16816(float* d, const uint32_t* a, uint32_t b0, uint32_t b1) {
    asm volatile("mma.sync.aligned.m16n8k16.row.col.f32.f16.f16.f32 "
                 "{%0,%1,%2,%3},{%4,%5,%6,%7},{%8,%9},{%0,%1,%2,%3};"
                 : "+f"(d[0]), "+f"(d[1]), "+f"(d[2]), "+f"(d[3])
                 : "r"(a[0]), "r"(a[1]), "r"(a[2]), "r"(a[3]), "r"(b0), "r"(b1));
}

// ============================================================================
// prep: x fp32 -> fp16 streaming convert (straight layout only). grid 4096x256.
// ============================================================================
__global__ void __launch_bounds__(256) prep_kernel(const float* __restrict__ x) {
    const size_t i = ((size_t)blockIdx.x * 256 + threadIdx.x) * 16;
    __half hb[16];
#pragma unroll
    for (int j = 0; j < 4; j++) {
        float4 q = *(const float4*)(x + i + j * 4);
        hb[j * 4 + 0] = __float2half_rn(q.x);
        hb[j * 4 + 1] = __float2half_rn(q.y);
        hb[j * 4 + 2] = __float2half_rn(q.z);
        hb[j * 4 + 3] = __float2half_rn(q.w);
    }
    *(float4*)(g_xh + i) = ((const float4*)hb)[0];
    *(float4*)(g_xh + i + 8) = ((const float4*)hb)[1];
}

// ============================================================================
// chain: C_s[pq][u*64+v] fp16. grid(64 u, 3 s), 256 thr = (p,q)
//   s0: u=n1,v=n2: core1[u][p][t]*core2[v][t][q]
//   s1: u=n0,v=n2: core2[v][p][t]*core0[u][t][q]
//   s2: u=n1,v=n0: core0[v][p][t]*core1[u][t][q]
// ============================================================================
__global__ void __launch_bounds__(256) chain_kernel(const float* __restrict__ c0,
                                                    const float* __restrict__ c1,
                                                    const float* __restrict__ c2) {
    const int u = blockIdx.x, s = blockIdx.y, tid = threadIdx.x;
    const int p = tid >> 4, q = tid & 15;
    __shared__ float U[256], V[256];
    const float* Uc = (s == 1) ? c0 : c1;
    const float* Vc = (s == 2) ? c0 : c2;
    U[tid] = Uc[u * 256 + tid];
    __syncthreads();
    float vals[64];
#pragma unroll
    for (int v = 0; v < 64; v++) {
        V[tid] = Vc[v * 256 + tid];
        __syncthreads();
        float acc = 0.f;
        if (s == 0) {
#pragma unroll
            for (int t = 0; t < 16; t++) acc += U[p * 16 + t] * V[t * 16 + q];
        } else {
#pragma unroll
            for (int t = 0; t < 16; t++) acc += V[p * 16 + t] * U[t * 16 + q];
        }
        vals[v] = acc;
        __syncthreads();
    }
    const size_t o = (size_t)s * 1048576 + (size_t)tid * 4096 + (size_t)u * 64;
#pragma unroll
    for (int v = 0; v < 64; v++) g_c[o + v] = __float2half_rn(vals[v]);
}

// ============================================================================
// GEMM: grid(64 m, 2 n, 12 = skip*4 + kq), 128 threads (4 warps 2x2, warp tile
// 32x64). Partial -> g_part; 4th arrival per tile combines -> out.
// ============================================================================
template <int SKIP>
__device__ __forceinline__ void gemm_body(float* __restrict__ out,
                                          float* __restrict__ part, int kbase,
                                          unsigned* s_old) {
    extern __shared__ char smem[];
    const uint32_t sb = smem_u32(smem);
    const int tid = threadIdx.x, lane = tid & 31, wid = tid >> 5;
    const int wm = wid >> 1, wn = wid & 1;
    const int m0 = blockIdx.x * BM, n0 = blockIdx.y * BN;

    const __half* B = g_c + (size_t)SKIP * 1048576;

    auto load = [&](int chunk, int st) {  // chunk: global 0..127
        const uint32_t stg = sb + st * STAGE_BYTES;
        if (SKIP == 2) {
            // A^T tile: 32 k-rows (n0 within chunk) x 64 m (n2), rows 128B
            const int bb = m0 >> 6;
#pragma unroll
            for (int i = 0; i < 2; i++) {
                const int lin = tid + i * 128;
                const int r = lin >> 3, c = lin & 7;  // r: k-row, c: 16B seg
                const __half* g = g_xh + ((size_t)bb << 18) +
                                  ((size_t)(((chunk & 1) << 5) + r) << 12) +
                                  ((chunk >> 1) << 6) + (c << 3);
                cp_async16(stg + r * TPITCH + c * 16, g);
            }
        } else {
#pragma unroll
            for (int i = 0; i < 2; i++) {
                const int lin = tid + i * 128;
                const int r = lin >> 2, c = lin & 3;
                size_t offA;
                if (SKIP == 1) {
                    const int bb = m0 >> 6;  // one b per CTA (BM=64)
                    offA = ((size_t)bb << 18) + ((size_t)(chunk >> 1) << 12) + (r << 6) +
                           ((chunk & 1) << 5) + (c << 3);
                } else {
                    offA = ((size_t)(m0 + r) << 12) + (chunk << 5) + (c << 3);
                }
                cp_async16(stg + r * PITCH + c * 16, g_xh + offA);
            }
        }
#pragma unroll
        for (int i = 0; i < 4; i++) {
            const int lin = tid + i * 128;
            const int r = lin >> 2, c = lin & 3;
            cp_async16(stg + APART + r * PITCH + c * 16,
                       B + ((size_t)(n0 + r) << 12) + (chunk << 5) + (c << 3));
        }
        cp_commit();
    };

    float acc[2][8][4];
#pragma unroll
    for (int fm = 0; fm < 2; fm++)
#pragma unroll
        for (int fn = 0; fn < 8; fn++)
#pragma unroll
            for (int j = 0; j < 4; j++) acc[fm][fn][j] = 0.f;

    load(kbase + 0, 0);
    load(kbase + 1, 1);

    // A fragment smem offsets
    const uint32_t aoff = (wm * 32 + (lane & 15)) * PITCH + (lane >> 4) * 16;  // skips 0,1
    const uint32_t atoff = ((lane & 7) + ((lane >> 4) << 3)) * TPITCH +
                           ((lane >> 3) & 1) * 16 + wm * 64;                    // skip 2 (trans)
    const uint32_t boff = APART + (wn * 64 + (lane & 15)) * PITCH + (lane >> 4) * 16;

    for (int c = 0; c < KCHUNKS_QTR; c++) {
        const int st = c % NSTAGE;
        if (c < KCHUNKS_QTR - 1) cp_wait<1>();
        else                     cp_wait<0>();
        __syncthreads();
        if (c + 2 < KCHUNKS_QTR) load(kbase + c + 2, (c + 2) % NSTAGE);

        const uint32_t stg = sb + st * STAGE_BYTES;
#pragma unroll
        for (int ks = 0; ks < 2; ks++) {
            uint32_t b[4][4];
#pragma unroll
            for (int fp = 0; fp < 4; fp++)
                ldsm_x4(b[fp][0], b[fp][1], b[fp][2], b[fp][3],
                        stg + boff + fp * (16 * PITCH) + ks * 32);
#pragma unroll
            for (int fm = 0; fm < 2; fm++) {
                uint32_t a4[4];
                if (SKIP == 2)
                    ldsm_x4_t(a4[0], a4[1], a4[2], a4[3],
                              stg + atoff + ks * (16 * TPITCH) + fm * 32);
                else
                    ldsm_x4(a4[0], a4[1], a4[2], a4[3],
                            stg + aoff + fm * (16 * PITCH) + ks * 32);
#pragma unroll
                for (int fn = 0; fn < 8; fn++)
                    mma16816(acc[fm][fn], a4, b[fn >> 1][fn & 1], b[fn >> 1][(fn & 1) + 2]);
            }
        }
    }

    // ---- epilogue: store this quarter's partial (plain stores, idempotent) ----
    const int rbase = m0 + wm * 32 + (lane >> 2);
    const int cbase = n0 + wn * 64 + (lane & 3) * 2;
#pragma unroll
    for (int fm = 0; fm < 2; fm++)
#pragma unroll
        for (int fn = 0; fn < 8; fn++) {
            const int rr = rbase + fm * 16;
            const int cc = cbase + fn * 8;
            *(float2*)(part + (size_t)rr * 256 + cc) = make_float2(acc[fm][fn][0], acc[fm][fn][1]);
            *(float2*)(part + (size_t)(rr + 8) * 256 + cc) = make_float2(acc[fm][fn][2], acc[fm][fn][3]);
        }

    // ---- ticket: 4th arrival for this (skip, mtile, ntile) combines -> out ----
    __threadfence();
    __syncthreads();
    if (tid == 0)
        *s_old = atomicAdd(&g_ticket[SKIP * 128 + blockIdx.x * 2 + blockIdx.y], 1u);
    __syncthreads();
    if ((*s_old & 3u) == 3u) {
        __threadfence();
        const float* p0 = g_part + (size_t)SKIP * 1048576;
        float* outp = out + (size_t)SKIP * 1048576;
#pragma unroll
        for (int it = 0; it < 16; it++) {
            const int lin = tid + it * 128;
            const int row = lin >> 5, c4 = (lin & 31) * 4;
            const size_t off = (size_t)(m0 + row) * 256 + n0 + c4;
            float4 a = *(const float4*)(p0 + off);
            float4 b = *(const float4*)(p0 + 3145728 + off);
            float4 cc = *(const float4*)(p0 + 2u * 3145728 + off);
            float4 d = *(const float4*)(p0 + 3u * 3145728 + off);
            *(float4*)(outp + off) = make_float4((a.x + b.x) + (cc.x + d.x),
                                                 (a.y + b.y) + (cc.y + d.y),
                                                 (a.z + b.z) + (cc.z + d.z),
                                                 (a.w + b.w) + (cc.w + d.w));
        }
    }
}

__global__ void __launch_bounds__(128, 4) gemm_kernel(float* __restrict__ out) {
    __shared__ unsigned s_old;
    const int skip = blockIdx.z >> 2;
    const int kq = blockIdx.z & 3;
    float* part = g_part + (size_t)kq * 3145728 + (size_t)skip * 1048576;
    const int kbase = kq * KCHUNKS_QTR;
    if (skip == 0)      gemm_body<0>(out, part, kbase, &s_old);
    else if (skip == 1) gemm_body<1>(out, part, kbase, &s_old);
    else                gemm_body<2>(out, part, kbase, &s_old);
}

// ----------------------------------------------------------------------------
extern "C" void kernel_launch(void* const* d_in, const int* in_sizes, int n_in,
                              void* d_out, int out_size) {
    const float* x  = (const float*)d_in[0];
    const float* c0 = (const float*)d_in[1];
    const float* c1 = (const float*)d_in[2];
    const float* c2 = (const float*)d_in[3];
    float* out = (float*)d_out;

    cudaFuncSetAttribute(gemm_kernel, cudaFuncAttributeMaxDynamicSharedMemorySize, SMEM_TOTAL);
    chain_kernel<<<dim3(64, 3), 256>>>(c0, c1, c2);
    prep_kernel<<<4096, 256>>>(x);
    gemm_kernel<<<dim3(64, 2, 12), 128, SMEM_TOTAL>>>(out);
}

// round 14
// speedup vs baseline: 4.3561x; 1.1595x over previous
#include <cuda_runtime.h>
#include <cuda_fp16.h>
#include <cstdint>

// ============================================================================
// node_s (4096x256) = X_s (4096x4096) @ C_s^T, single fp16 product.
//   skip0: rows (b,n0), k=(n1,n2) -> A rows from g_xh straight
//   skip1: rows (b,n1), k=(n0,n2) -> gather 64-row blocks of g_xh
//   skip2: rows (b,n2), k=(n1,n0) -> A^T tiles from g_xh + ldmatrix.trans
// SPLIT-K x4 (1536 CTAs); partials in g_part; 4th-arriving CTA per tile
// (threadfence+ticket) sums partials -> out.
// chain: fully parallel, 1 sync, vectorized stores (round-14 rewrite).
// ============================================================================

#define BM 64
#define BN 128
#define KCHUNKS_QTR 32              // 1024 K per quarter, chunks of 32
#define PITCH 80                    // B/A rows: 64B + 16B pad
#define TPITCH 144                  // skip2 A^T rows: 128B + 16B pad
#define APART (BM * PITCH)          // 5120 (skip2 uses 32*144=4608 of it)
#define STAGE_BYTES (APART + BN * PITCH)  // 15360
#define NSTAGE 3
#define SMEM_TOTAL (STAGE_BYTES * NSTAGE)  // 46080

// ---- scratch (device globals: no allocation) ----
__device__ __align__(1024) __half g_xh[16777216];        // [b][n0][n1][n2]
__device__ __align__(1024) __half g_c[3u * 256 * 4096];  // chains [s][pq][k]
__device__ __align__(1024) float g_part[4u * 3145728];   // [kq][skip][m][n]
__device__ unsigned int g_ticket[384];                   // [skip][mtile][ntile]

// ---- PTX helpers ----
__device__ __forceinline__ uint32_t smem_u32(const void* p) {
    uint32_t a;
    asm("{ .reg .u64 t; cvta.to.shared.u64 t, %1; cvt.u32.u64 %0, t; }" : "=r"(a) : "l"(p));
    return a;
}
__device__ __forceinline__ void cp_async16(uint32_t s, const void* g) {
    asm volatile("cp.async.cg.shared.global [%0], [%1], 16;\n" :: "r"(s), "l"(g));
}
__device__ __forceinline__ void cp_commit() { asm volatile("cp.async.commit_group;\n" ::: "memory"); }
template <int N> __device__ __forceinline__ void cp_wait() {
    asm volatile("cp.async.wait_group %0;\n" :: "n"(N) : "memory");
}
__device__ __forceinline__ void ldsm_x4(uint32_t& r0, uint32_t& r1, uint32_t& r2,
                                        uint32_t& r3, uint32_t addr) {
    asm volatile("ldmatrix.sync.aligned.m8n8.x4.shared.b16 {%0,%1,%2,%3}, [%4];"
                 : "=r"(r0), "=r"(r1), "=r"(r2), "=r"(r3) : "r"(addr));
}
__device__ __forceinline__ void ldsm_x4_t(uint32_t& r0, uint32_t& r1, uint32_t& r2,
                                          uint32_t& r3, uint32_t addr) {
    asm volatile("ldmatrix.sync.aligned.m8n8.x4.trans.shared.b16 {%0,%1,%2,%3}, [%4];"
                 : "=r"(r0), "=r"(r1), "=r"(r2), "=r"(r3) : "r"(addr));
}
__device__ __forceinline__ void mma16816(float* d, const uint32_t* a, uint32_t b0, uint32_t b1) {
    asm volatile("mma.sync.aligned.m16n8k16.row.col.f32.f16.f16.f32 "
                 "{%0,%1,%2,%3},{%4,%5,%6,%7},{%8,%9},{%0,%1,%2,%3};"
                 : "+f"(d[0]), "+f"(d[1]), "+f"(d[2]), "+f"(d[3])
                 : "r"(a[0]), "r"(a[1]), "r"(a[2]), "r"(a[3]), "r"(b0), "r"(b1));
}

// ============================================================================
// prep: x fp32 -> fp16 streaming convert (straight layout only). grid 4096x256.
// ============================================================================
__global__ void __launch_bounds__(256) prep_kernel(const float* __restrict__ x) {
    const size_t i = ((size_t)blockIdx.x * 256 + threadIdx.x) * 16;
    __half hb[16];
#pragma unroll
    for (int j = 0; j < 4; j++) {
        float4 q = *(const float4*)(x + i + j * 4);
        hb[j * 4 + 0] = __float2half_rn(q.x);
        hb[j * 4 + 1] = __float2half_rn(q.y);
        hb[j * 4 + 2] = __float2half_rn(q.z);
        hb[j * 4 + 3] = __float2half_rn(q.w);
    }
    *(float4*)(g_xh + i) = ((const float4*)hb)[0];
    *(float4*)(g_xh + i + 8) = ((const float4*)hb)[1];
}

// ============================================================================
// chain: C_s[pq][u*64+v] fp16, fully parallel. grid(512, 3): u = bx>>3,
// vg = bx&7 (8 v per block). 256 thr = (p,q). One sync; 16B vectorized store.
//   s0: u=n1,v=n2: core1[u][p][t]*core2[v][t][q]
//   s1: u=n0,v=n2: core2[v][p][t]*core0[u][t][q]
//   s2: u=n1,v=n0: core0[v][p][t]*core1[u][t][q]
// ============================================================================
__global__ void __launch_bounds__(256) chain_kernel(const float* __restrict__ c0,
                                                    const float* __restrict__ c1,
                                                    const float* __restrict__ c2) {
    const int u = blockIdx.x >> 3, vg = blockIdx.x & 7, s = blockIdx.y;
    const int tid = threadIdx.x;
    const int p = tid >> 4, q = tid & 15;
    __shared__ float U[256], V[8][256];
    const float* Uc = (s == 1) ? c0 : c1;
    const float* Vc = (s == 2) ? c0 : c2;
    U[tid] = Uc[u * 256 + tid];
#pragma unroll
    for (int j = 0; j < 8; j++) V[j][tid] = Vc[(vg * 8 + j) * 256 + tid];
    __syncthreads();

    __half vals[8];
#pragma unroll
    for (int j = 0; j < 8; j++) {
        float acc = 0.f;
        if (s == 0) {
#pragma unroll
            for (int t = 0; t < 16; t++) acc += U[p * 16 + t] * V[j][t * 16 + q];
        } else {
#pragma unroll
            for (int t = 0; t < 16; t++) acc += V[j][p * 16 + t] * U[t * 16 + q];
        }
        vals[j] = __float2half_rn(acc);
    }
    // v contiguous in g_c for fixed (s, pq, u): one 16B store
    const size_t o = (size_t)s * 1048576 + (size_t)tid * 4096 + (size_t)u * 64 + vg * 8;
    *(float4*)(g_c + o) = *(const float4*)vals;
}

// ============================================================================
// GEMM: grid(64 m, 2 n, 12 = skip*4 + kq), 128 threads (4 warps 2x2, warp tile
// 32x64). Partial -> g_part; 4th arrival per tile combines -> out.
// ============================================================================
template <int SKIP>
__device__ __forceinline__ void gemm_body(float* __restrict__ out,
                                          float* __restrict__ part, int kbase,
                                          unsigned* s_old) {
    extern __shared__ char smem[];
    const uint32_t sb = smem_u32(smem);
    const int tid = threadIdx.x, lane = tid & 31, wid = tid >> 5;
    const int wm = wid >> 1, wn = wid & 1;
    const int m0 = blockIdx.x * BM, n0 = blockIdx.y * BN;

    const __half* B = g_c + (size_t)SKIP * 1048576;

    auto load = [&](int chunk, int st) {  // chunk: global 0..127
        const uint32_t stg = sb + st * STAGE_BYTES;
        if (SKIP == 2) {
            // A^T tile: 32 k-rows (n0 within chunk) x 64 m (n2), rows 128B
            const int bb = m0 >> 6;
#pragma unroll
            for (int i = 0; i < 2; i++) {
                const int lin = tid + i * 128;
                const int r = lin >> 3, c = lin & 7;  // r: k-row, c: 16B seg
                const __half* g = g_xh + ((size_t)bb << 18) +
                                  ((size_t)(((chunk & 1) << 5) + r) << 12) +
                                  ((chunk >> 1) << 6) + (c << 3);
                cp_async16(stg + r * TPITCH + c * 16, g);
            }
        } else {
#pragma unroll
            for (int i = 0; i < 2; i++) {
                const int lin = tid + i * 128;
                const int r = lin >> 2, c = lin & 3;
                size_t offA;
                if (SKIP == 1) {
                    const int bb = m0 >> 6;  // one b per CTA (BM=64)
                    offA = ((size_t)bb << 18) + ((size_t)(chunk >> 1) << 12) + (r << 6) +
                           ((chunk & 1) << 5) + (c << 3);
                } else {
                    offA = ((size_t)(m0 + r) << 12) + (chunk << 5) + (c << 3);
                }
                cp_async16(stg + r * PITCH + c * 16, g_xh + offA);
            }
        }
#pragma unroll
        for (int i = 0; i < 4; i++) {
            const int lin = tid + i * 128;
            const int r = lin >> 2, c = lin & 3;
            cp_async16(stg + APART + r * PITCH + c * 16,
                       B + ((size_t)(n0 + r) << 12) + (chunk << 5) + (c << 3));
        }
        cp_commit();
    };

    float acc[2][8][4];
#pragma unroll
    for (int fm = 0; fm < 2; fm++)
#pragma unroll
        for (int fn = 0; fn < 8; fn++)
#pragma unroll
            for (int j = 0; j < 4; j++) acc[fm][fn][j] = 0.f;

    load(kbase + 0, 0);
    load(kbase + 1, 1);

    const uint32_t aoff = (wm * 32 + (lane & 15)) * PITCH + (lane >> 4) * 16;  // skips 0,1
    const uint32_t atoff = ((lane & 7) + ((lane >> 4) << 3)) * TPITCH +
                           ((lane >> 3) & 1) * 16 + wm * 64;                    // skip 2 (trans)
    const uint32_t boff = APART + (wn * 64 + (lane & 15)) * PITCH + (lane >> 4) * 16;

    for (int c = 0; c < KCHUNKS_QTR; c++) {
        const int st = c % NSTAGE;
        if (c < KCHUNKS_QTR - 1) cp_wait<1>();
        else                     cp_wait<0>();
        __syncthreads();
        if (c + 2 < KCHUNKS_QTR) load(kbase + c + 2, (c + 2) % NSTAGE);

        const uint32_t stg = sb + st * STAGE_BYTES;
#pragma unroll
        for (int ks = 0; ks < 2; ks++) {
            uint32_t b[4][4];
#pragma unroll
            for (int fp = 0; fp < 4; fp++)
                ldsm_x4(b[fp][0], b[fp][1], b[fp][2], b[fp][3],
                        stg + boff + fp * (16 * PITCH) + ks * 32);
#pragma unroll
            for (int fm = 0; fm < 2; fm++) {
                uint32_t a4[4];
                if (SKIP == 2)
                    ldsm_x4_t(a4[0], a4[1], a4[2], a4[3],
                              stg + atoff + ks * (16 * TPITCH) + fm * 32);
                else
                    ldsm_x4(a4[0], a4[1], a4[2], a4[3],
                            stg + aoff + fm * (16 * PITCH) + ks * 32);
#pragma unroll
                for (int fn = 0; fn < 8; fn++)
                    mma16816(acc[fm][fn], a4, b[fn >> 1][fn & 1], b[fn >> 1][(fn & 1) + 2]);
            }
        }
    }

    // ---- epilogue: store this quarter's partial (plain stores, idempotent) ----
    const int rbase = m0 + wm * 32 + (lane >> 2);
    const int cbase = n0 + wn * 64 + (lane & 3) * 2;
#pragma unroll
    for (int fm = 0; fm < 2; fm++)
#pragma unroll
        for (int fn = 0; fn < 8; fn++) {
            const int rr = rbase + fm * 16;
            const int cc = cbase + fn * 8;
            *(float2*)(part + (size_t)rr * 256 + cc) = make_float2(acc[fm][fn][0], acc[fm][fn][1]);
            *(float2*)(part + (size_t)(rr + 8) * 256 + cc) = make_float2(acc[fm][fn][2], acc[fm][fn][3]);
        }

    // ---- ticket: 4th arrival for this (skip, mtile, ntile) combines -> out ----
    __threadfence();
    __syncthreads();
    if (tid == 0)
        *s_old = atomicAdd(&g_ticket[SKIP * 128 + blockIdx.x * 2 + blockIdx.y], 1u);
    __syncthreads();
    if ((*s_old & 3u) == 3u) {
        __threadfence();
        const float* p0 = g_part + (size_t)SKIP * 1048576;
        float* outp = out + (size_t)SKIP * 1048576;
#pragma unroll
        for (int it = 0; it < 16; it++) {
            const int lin = tid + it * 128;
            const int row = lin >> 5, c4 = (lin & 31) * 4;
            const size_t off = (size_t)(m0 + row) * 256 + n0 + c4;
            float4 a = *(const float4*)(p0 + off);
            float4 b = *(const float4*)(p0 + 3145728 + off);
            float4 cc = *(const float4*)(p0 + 2u * 3145728 + off);
            float4 d = *(const float4*)(p0 + 3u * 3145728 + off);
            *(float4*)(outp + off) = make_float4((a.x + b.x) + (cc.x + d.x),
                                                 (a.y + b.y) + (cc.y + d.y),
                                                 (a.z + b.z) + (cc.z + d.z),
                                                 (a.w + b.w) + (cc.w + d.w));
        }
    }
}

__global__ void __launch_bounds__(128, 4) gemm_kernel(float* __restrict__ out) {
    __shared__ unsigned s_old;
    const int skip = blockIdx.z >> 2;
    const int kq = blockIdx.z & 3;
    float* part = g_part + (size_t)kq * 3145728 + (size_t)skip * 1048576;
    const int kbase = kq * KCHUNKS_QTR;
    if (skip == 0)      gemm_body<0>(out, part, kbase, &s_old);
    else if (skip == 1) gemm_body<1>(out, part, kbase, &s_old);
    else                gemm_body<2>(out, part, kbase, &s_old);
}

// ----------------------------------------------------------------------------
extern "C" void kernel_launch(void* const* d_in, const int* in_sizes, int n_in,
                              void* d_out, int out_size) {
    const float* x  = (const float*)d_in[0];
    const float* c0 = (const float*)d_in[1];
    const float* c1 = (const float*)d_in[2];
    const float* c2 = (const float*)d_in[3];
    float* out = (float*)d_out;

    cudaFuncSetAttribute(gemm_kernel, cudaFuncAttributeMaxDynamicSharedMemorySize, SMEM_TOTAL);
    chain_kernel<<<dim3(512, 3), 256>>>(c0, c1, c2);
    prep_kernel<<<4096, 256>>>(x);
    gemm_kernel<<<dim3(64, 2, 12), 128, SMEM_TOTAL>>>(out);
}

// round 15
// speedup vs baseline: 4.4177x; 1.0141x over previous
#include <cuda_runtime.h>
#include <cuda_fp16.h>
#include <cstdint>

// ============================================================================
// node_s (4096x256) = X_s (4096x4096) @ C_s^T, single fp16 product.
//   skip0: rows (b,n0), k=(n1,n2) -> A rows from g_xh straight
//   skip1: rows (b,n1), k=(n0,n2) -> gather 64-row blocks of g_xh
//   skip2: rows (b,n2), k=(n1,n0) -> A^T tiles from g_xh + ldmatrix.trans
// SPLIT-K x4 (1536 CTAs); partials in g_part; 4th-arriving CTA per tile
// (threadfence+ticket) sums partials -> out.
// prep (x->fp16 streaming) and chain (parallel, 31-reg) FUSED in one launch.
// ============================================================================

#define BM 64
#define BN 128
#define KCHUNKS_QTR 32              // 1024 K per quarter, chunks of 32
#define PITCH 80                    // B/A rows: 64B + 16B pad
#define TPITCH 144                  // skip2 A^T rows: 128B + 16B pad
#define APART (BM * PITCH)          // 5120 (skip2 uses 32*144=4608 of it)
#define STAGE_BYTES (APART + BN * PITCH)  // 15360
#define NSTAGE 3
#define SMEM_TOTAL (STAGE_BYTES * NSTAGE)  // 46080

// ---- scratch (device globals: no allocation) ----
__device__ __align__(1024) __half g_xh[16777216];        // [b][n0][n1][n2]
__device__ __align__(1024) __half g_c[3u * 256 * 4096];  // chains [s][pq][k]
__device__ __align__(1024) float g_part[4u * 3145728];   // [kq][skip][m][n]
__device__ unsigned int g_ticket[384];                   // [skip][mtile][ntile]

// ---- PTX helpers ----
__device__ __forceinline__ uint32_t smem_u32(const void* p) {
    uint32_t a;
    asm("{ .reg .u64 t; cvta.to.shared.u64 t, %1; cvt.u32.u64 %0, t; }" : "=r"(a) : "l"(p));
    return a;
}
__device__ __forceinline__ void cp_async16(uint32_t s, const void* g) {
    asm volatile("cp.async.cg.shared.global [%0], [%1], 16;\n" :: "r"(s), "l"(g));
}
__device__ __forceinline__ void cp_commit() { asm volatile("cp.async.commit_group;\n" ::: "memory"); }
template <int N> __device__ __forceinline__ void cp_wait() {
    asm volatile("cp.async.wait_group %0;\n" :: "n"(N) : "memory");
}
__device__ __forceinline__ void ldsm_x4(uint32_t& r0, uint32_t& r1, uint32_t& r2,
                                        uint32_t& r3, uint32_t addr) {
    asm volatile("ldmatrix.sync.aligned.m8n8.x4.shared.b16 {%0,%1,%2,%3}, [%4];"
                 : "=r"(r0), "=r"(r1), "=r"(r2), "=r"(r3) : "r"(addr));
}
__device__ __forceinline__ void ldsm_x4_t(uint32_t& r0, uint32_t& r1, uint32_t& r2,
                                          uint32_t& r3, uint32_t addr) {
    asm volatile("ldmatrix.sync.aligned.m8n8.x4.trans.shared.b16 {%0,%1,%2,%3}, [%4];"
                 : "=r"(r0), "=r"(r1), "=r"(r2), "=r"(r3) : "r"(addr));
}
__device__ __forceinline__ void mma16816(float* d, const uint32_t* a, uint32_t b0, uint32_t b1) {
    asm volatile("mma.sync.aligned.m16n8k16.row.col.f32.f16.f16.f32 "
                 "{%0,%1,%2,%3},{%4,%5,%6,%7},{%8,%9},{%0,%1,%2,%3};"
                 : "+f"(d[0]), "+f"(d[1]), "+f"(d[2]), "+f"(d[3])
                 : "r"(a[0]), "r"(a[1]), "r"(a[2]), "r"(a[3]), "r"(b0), "r"(b1));
}

// ============================================================================
// prep+chain fused, grid 5632 x 256 (1D):
//   bx < 4096: prep  — x fp32 -> fp16 streaming (16 elems/thread)
//   bx >= 4096: chain — idx=bx-4096: s=idx>>9, u=(idx&511)>>3, vg=idx&7
//     s0: u=n1,v=n2: core1[u][p][t]*core2[v][t][q]
//     s1: u=n0,v=n2: core2[v][p][t]*core0[u][t][q]
//     s2: u=n1,v=n0: core0[v][p][t]*core1[u][t][q]
// ============================================================================
__global__ void __launch_bounds__(256) prep_chain_kernel(const float* __restrict__ x,
                                                         const float* __restrict__ c0,
                                                         const float* __restrict__ c1,
                                                         const float* __restrict__ c2) {
    const int tid = threadIdx.x;
    if (blockIdx.x < 4096) {
        const size_t i = ((size_t)blockIdx.x * 256 + tid) * 16;
        __half hb[16];
#pragma unroll
        for (int j = 0; j < 4; j++) {
            float4 q = *(const float4*)(x + i + j * 4);
            hb[j * 4 + 0] = __float2half_rn(q.x);
            hb[j * 4 + 1] = __float2half_rn(q.y);
            hb[j * 4 + 2] = __float2half_rn(q.z);
            hb[j * 4 + 3] = __float2half_rn(q.w);
        }
        *(float4*)(g_xh + i) = ((const float4*)hb)[0];
        *(float4*)(g_xh + i + 8) = ((const float4*)hb)[1];
    } else {
        const int idx = blockIdx.x - 4096;
        const int s = idx >> 9, u = (idx & 511) >> 3, vg = idx & 7;
        const int p = tid >> 4, q = tid & 15;
        __shared__ float U[256], V[8][256];
        const float* Uc = (s == 1) ? c0 : c1;
        const float* Vc = (s == 2) ? c0 : c2;
        U[tid] = Uc[u * 256 + tid];
#pragma unroll
        for (int j = 0; j < 8; j++) V[j][tid] = Vc[(vg * 8 + j) * 256 + tid];
        __syncthreads();

        __half vals[8];
#pragma unroll
        for (int j = 0; j < 8; j++) {
            float acc = 0.f;
            if (s == 0) {
#pragma unroll
                for (int t = 0; t < 16; t++) acc += U[p * 16 + t] * V[j][t * 16 + q];
            } else {
#pragma unroll
                for (int t = 0; t < 16; t++) acc += V[j][p * 16 + t] * U[t * 16 + q];
            }
            vals[j] = __float2half_rn(acc);
        }
        const size_t o = (size_t)s * 1048576 + (size_t)tid * 4096 + (size_t)u * 64 + vg * 8;
        *(float4*)(g_c + o) = *(const float4*)vals;
    }
}

// ============================================================================
// GEMM: grid(64 m, 2 n, 12 = skip*4 + kq), 128 threads (4 warps 2x2, warp tile
// 32x64). Partial -> g_part; 4th arrival per tile combines -> out.
// ============================================================================
template <int SKIP>
__device__ __forceinline__ void gemm_body(float* __restrict__ out,
                                          float* __restrict__ part, int kbase,
                                          unsigned* s_old) {
    extern __shared__ char smem[];
    const uint32_t sb = smem_u32(smem);
    const int tid = threadIdx.x, lane = tid & 31, wid = tid >> 5;
    const int wm = wid >> 1, wn = wid & 1;
    const int m0 = blockIdx.x * BM, n0 = blockIdx.y * BN;

    const __half* B = g_c + (size_t)SKIP * 1048576;

    auto load = [&](int chunk, int st) {  // chunk: global 0..127
        const uint32_t stg = sb + st * STAGE_BYTES;
        if (SKIP == 2) {
            // A^T tile: 32 k-rows (n0 within chunk) x 64 m (n2), rows 128B
            const int bb = m0 >> 6;
#pragma unroll
            for (int i = 0; i < 2; i++) {
                const int lin = tid + i * 128;
                const int r = lin >> 3, c = lin & 7;  // r: k-row, c: 16B seg
                const __half* g = g_xh + ((size_t)bb << 18) +
                                  ((size_t)(((chunk & 1) << 5) + r) << 12) +
                                  ((chunk >> 1) << 6) + (c << 3);
                cp_async16(stg + r * TPITCH + c * 16, g);
            }
        } else {
#pragma unroll
            for (int i = 0; i < 2; i++) {
                const int lin = tid + i * 128;
                const int r = lin >> 2, c = lin & 3;
                size_t offA;
                if (SKIP == 1) {
                    const int bb = m0 >> 6;  // one b per CTA (BM=64)
                    offA = ((size_t)bb << 18) + ((size_t)(chunk >> 1) << 12) + (r << 6) +
                           ((chunk & 1) << 5) + (c << 3);
                } else {
                    offA = ((size_t)(m0 + r) << 12) + (chunk << 5) + (c << 3);
                }
                cp_async16(stg + r * PITCH + c * 16, g_xh + offA);
            }
        }
#pragma unroll
        for (int i = 0; i < 4; i++) {
            const int lin = tid + i * 128;
            const int r = lin >> 2, c = lin & 3;
            cp_async16(stg + APART + r * PITCH + c * 16,
                       B + ((size_t)(n0 + r) << 12) + (chunk << 5) + (c << 3));
        }
        cp_commit();
    };

    float acc[2][8][4];
#pragma unroll
    for (int fm = 0; fm < 2; fm++)
#pragma unroll
        for (int fn = 0; fn < 8; fn++)
#pragma unroll
            for (int j = 0; j < 4; j++) acc[fm][fn][j] = 0.f;

    load(kbase + 0, 0);
    load(kbase + 1, 1);

    const uint32_t aoff = (wm * 32 + (lane & 15)) * PITCH + (lane >> 4) * 16;  // skips 0,1
    const uint32_t atoff = ((lane & 7) + ((lane >> 4) << 3)) * TPITCH +
                           ((lane >> 3) & 1) * 16 + wm * 64;                    // skip 2 (trans)
    const uint32_t boff = APART + (wn * 64 + (lane & 15)) * PITCH + (lane >> 4) * 16;

    for (int c = 0; c < KCHUNKS_QTR; c++) {
        const int st = c % NSTAGE;
        if (c < KCHUNKS_QTR - 1) cp_wait<1>();
        else                     cp_wait<0>();
        __syncthreads();
        if (c + 2 < KCHUNKS_QTR) load(kbase + c + 2, (c + 2) % NSTAGE);

        const uint32_t stg = sb + st * STAGE_BYTES;
#pragma unroll
        for (int ks = 0; ks < 2; ks++) {
            uint32_t b[4][4];
#pragma unroll
            for (int fp = 0; fp < 4; fp++)
                ldsm_x4(b[fp][0], b[fp][1], b[fp][2], b[fp][3],
                        stg + boff + fp * (16 * PITCH) + ks * 32);
#pragma unroll
            for (int fm = 0; fm < 2; fm++) {
                uint32_t a4[4];
                if (SKIP == 2)
                    ldsm_x4_t(a4[0], a4[1], a4[2], a4[3],
                              stg + atoff + ks * (16 * TPITCH) + fm * 32);
                else
                    ldsm_x4(a4[0], a4[1], a4[2], a4[3],
                            stg + aoff + fm * (16 * PITCH) + ks * 32);
#pragma unroll
                for (int fn = 0; fn < 8; fn++)
                    mma16816(acc[fm][fn], a4, b[fn >> 1][fn & 1], b[fn >> 1][(fn & 1) + 2]);
            }
        }
    }

    // ---- epilogue: store this quarter's partial (plain stores, idempotent) ----
    const int rbase = m0 + wm * 32 + (lane >> 2);
    const int cbase = n0 + wn * 64 + (lane & 3) * 2;
#pragma unroll
    for (int fm = 0; fm < 2; fm++)
#pragma unroll
        for (int fn = 0; fn < 8; fn++) {
            const int rr = rbase + fm * 16;
            const int cc = cbase + fn * 8;
            *(float2*)(part + (size_t)rr * 256 + cc) = make_float2(acc[fm][fn][0], acc[fm][fn][1]);
            *(float2*)(part + (size_t)(rr + 8) * 256 + cc) = make_float2(acc[fm][fn][2], acc[fm][fn][3]);
        }

    // ---- ticket: 4th arrival for this (skip, mtile, ntile) combines -> out ----
    __threadfence();
    __syncthreads();
    if (tid == 0)
        *s_old = atomicAdd(&g_ticket[SKIP * 128 + blockIdx.x * 2 + blockIdx.y], 1u);
    __syncthreads();
    if ((*s_old & 3u) == 3u) {
        __threadfence();
        const float* p0 = g_part + (size_t)SKIP * 1048576;
        float* outp = out + (size_t)SKIP * 1048576;
#pragma unroll
        for (int it = 0; it < 16; it++) {
            const int lin = tid + it * 128;
            const int row = lin >> 5, c4 = (lin & 31) * 4;
            const size_t off = (size_t)(m0 + row) * 256 + n0 + c4;
            float4 a = *(const float4*)(p0 + off);
            float4 b = *(const float4*)(p0 + 3145728 + off);
            float4 cc = *(const float4*)(p0 + 2u * 3145728 + off);
            float4 d = *(const float4*)(p0 + 3u * 3145728 + off);
            *(float4*)(outp + off) = make_float4((a.x + b.x) + (cc.x + d.x),
                                                 (a.y + b.y) + (cc.y + d.y),
                                                 (a.z + b.z) + (cc.z + d.z),
                                                 (a.w + b.w) + (cc.w + d.w));
        }
    }
}

__global__ void __launch_bounds__(128, 4) gemm_kernel(float* __restrict__ out) {
    __shared__ unsigned s_old;
    const int skip = blockIdx.z >> 2;
    const int kq = blockIdx.z & 3;
    float* part = g_part + (size_t)kq * 3145728 + (size_t)skip * 1048576;
    const int kbase = kq * KCHUNKS_QTR;
    if (skip == 0)      gemm_body<0>(out, part, kbase, &s_old);
    else if (skip == 1) gemm_body<1>(out, part, kbase, &s_old);
    else                gemm_body<2>(out, part, kbase, &s_old);
}

// ----------------------------------------------------------------------------
extern "C" void kernel_launch(void* const* d_in, const int* in_sizes, int n_in,
                              void* d_out, int out_size) {
    const float* x  = (const float*)d_in[0];
    const float* c0 = (const float*)d_in[1];
    const float* c1 = (const float*)d_in[2];
    const float* c2 = (const float*)d_in[3];
    float* out = (float*)d_out;

    cudaFuncSetAttribute(gemm_kernel, cudaFuncAttributeMaxDynamicSharedMemorySize, SMEM_TOTAL);
    prep_chain_kernel<<<5632, 256>>>(x, c0, c1, c2);
    gemm_kernel<<<dim3(64, 2, 12), 128, SMEM_TOTAL>>>(out);
}